// round 3
// baseline (speedup 1.0000x reference)
#include <cuda_runtime.h>
#include <math.h>

#define N 8192
#define D 512
#define KSEL 16

#define BM 128
#define BN 128
#define BK 8
#define TM 8
#define TN 8
// 256 threads = (BM/TM) * (BN/TN) = 16 x 16

// ---------------------------------------------------------------------------
// Kernel 1: sim = X * X^T  (fp32 SIMT tiled GEMM, NT form)
// C[i][j] = sum_k X[i][k] * X[j][k]
// ---------------------------------------------------------------------------
__global__ __launch_bounds__(256) void gemm_xxT_kernel(
    const float* __restrict__ X, float* __restrict__ C)
{
    __shared__ float As[BK][BM];
    __shared__ float Bs[BK][BN];

    const int bx = blockIdx.x;  // col block
    const int by = blockIdx.y;  // row block
    const int tid = threadIdx.x;
    const int tx = tid & 15;    // 0..15 (col direction)
    const int ty = tid >> 4;    // 0..15 (row direction)

    // Global load mapping: one float4 of A and one of B per thread per k-tile.
    const int lrow = tid >> 1;       // 0..127
    const int lk   = (tid & 1) * 4;  // 0 or 4

    const float* Arow = X + (size_t)(by * BM + lrow) * D;
    const float* Brow = X + (size_t)(bx * BN + lrow) * D;

    float acc[TM][TN];
#pragma unroll
    for (int i = 0; i < TM; i++)
#pragma unroll
        for (int j = 0; j < TN; j++) acc[i][j] = 0.0f;

    for (int k0 = 0; k0 < D; k0 += BK) {
        float4 a = *(const float4*)(Arow + k0 + lk);
        float4 b = *(const float4*)(Brow + k0 + lk);
        As[lk + 0][lrow] = a.x;
        As[lk + 1][lrow] = a.y;
        As[lk + 2][lrow] = a.z;
        As[lk + 3][lrow] = a.w;
        Bs[lk + 0][lrow] = b.x;
        Bs[lk + 1][lrow] = b.y;
        Bs[lk + 2][lrow] = b.z;
        Bs[lk + 3][lrow] = b.w;
        __syncthreads();

#pragma unroll
        for (int k = 0; k < BK; k++) {
            float ar[TM], br[TN];
#pragma unroll
            for (int i = 0; i < TM; i++) ar[i] = As[k][ty * TM + i];
#pragma unroll
            for (int j = 0; j < TN; j++) br[j] = Bs[k][tx * TN + j];
#pragma unroll
            for (int i = 0; i < TM; i++)
#pragma unroll
                for (int j = 0; j < TN; j++)
                    acc[i][j] = fmaf(ar[i], br[j], acc[i][j]);
        }
        __syncthreads();
    }

    // Store 8x8 tile as two float4s per row.
#pragma unroll
    for (int i = 0; i < TM; i++) {
        size_t row = (size_t)(by * BM + ty * TM + i);
        float* cp = C + row * N + (bx * BN + tx * TN);
        float4 v0 = make_float4(acc[i][0], acc[i][1], acc[i][2], acc[i][3]);
        float4 v1 = make_float4(acc[i][4], acc[i][5], acc[i][6], acc[i][7]);
        *(float4*)(cp + 0) = v0;
        *(float4*)(cp + 4) = v1;
    }
}

// ---------------------------------------------------------------------------
// Kernel 2: per-row top-16 select + sparsify (in place on the adj region).
// One CTA per row. Row copied to smem, 16x iterative argmax with
// lowest-index tie-break (matches jax.lax.top_k), then zero row and scatter.
// ---------------------------------------------------------------------------
__global__ __launch_bounds__(256) void topk_row_kernel(float* __restrict__ adj)
{
    __shared__ float vals[N];           // 32 KB working copy
    __shared__ float rv[256];
    __shared__ int   ri[256];
    __shared__ float selv[KSEL];
    __shared__ int   seli[KSEL];

    const int row = blockIdx.x;
    float* rowp = adj + (size_t)row * N;
    const int tid = threadIdx.x;

    // Load row into smem (float4).
    for (int j = tid * 4; j < N; j += 256 * 4)
        *(float4*)&vals[j] = *(const float4*)&rowp[j];
    __syncthreads();

    for (int it = 0; it < KSEL; it++) {
        float best = -INFINITY;
        int bi = -1;
        for (int j = tid; j < N; j += 256) {
            float v = vals[j];
            if (v > best) { best = v; bi = j; }  // first (lowest) idx wins ties
        }
        rv[tid] = best;
        ri[tid] = bi;
        __syncthreads();
        if (tid == 0) {
            float b = rv[0];
            int idx = ri[0];
            for (int t = 1; t < 256; t++) {
                if (rv[t] > b || (rv[t] == b && ri[t] < idx)) {
                    b = rv[t];
                    idx = ri[t];
                }
            }
            selv[it] = b;
            seli[it] = idx;
            vals[idx] = -INFINITY;  // mask for next iteration
        }
        __syncthreads();
    }

    // Zero the whole row, then scatter the 16 kept values.
    const float4 z = make_float4(0.f, 0.f, 0.f, 0.f);
    for (int j = tid * 4; j < N; j += 256 * 4)
        *(float4*)&rowp[j] = z;
    __syncthreads();
    if (tid < KSEL)
        rowp[seli[tid]] = selv[tid];
}

// ---------------------------------------------------------------------------
// Launch
// ---------------------------------------------------------------------------
extern "C" void kernel_launch(void* const* d_in, const int* in_sizes, int n_in,
                              void* d_out, int out_size)
{
    const float* x = (const float*)d_in[0];
    float* out = (float*)d_out;

    // Output layout: [ x (N*D floats) | adj (N*N floats) ]
    float* out_x   = out;
    float* out_adj = out + (size_t)N * D;

    // 1) Copy x through.
    cudaMemcpyAsync(out_x, x, (size_t)N * D * sizeof(float),
                    cudaMemcpyDeviceToDevice, 0);

    // 2) sim = x @ x^T into the adj region.
    dim3 grid(N / BN, N / BM);
    gemm_xxT_kernel<<<grid, 256>>>(x, out_adj);

    // 3) Per-row top-16 sparsification in place.
    topk_row_kernel<<<N, 256>>>(out_adj);
}

// round 4
// speedup vs baseline: 4.3518x; 4.3518x over previous
#include <cuda_runtime.h>
#include <cuda_bf16.h>
#include <math.h>

#define N 8192
#define D 512
#define KSEL 16
#define NCAND 32

// ---------------- static device scratch (no runtime allocation) -----------
__device__ __align__(16) __nv_bfloat16 g_xb[(size_t)N * D];        // 8 MB
__device__ __align__(16) __nv_bfloat16 g_sim[(size_t)N * N];       // 128 MB
__device__ int g_cand[N * NCAND];                                  // 1 MB

// ---------------------------------------------------------------------------
// Kernel 0: convert x (fp32) -> bf16 scratch
// ---------------------------------------------------------------------------
__global__ __launch_bounds__(256) void convert_bf16_kernel(const float* __restrict__ x)
{
    int i4 = blockIdx.x * 256 + threadIdx.x;          // float4 index
    float4 v = ((const float4*)x)[i4];
    __nv_bfloat162 lo = __floats2bfloat162_rn(v.x, v.y);
    __nv_bfloat162 hi = __floats2bfloat162_rn(v.z, v.w);
    uint2 packed;
    packed.x = *(unsigned int*)&lo;
    packed.y = *(unsigned int*)&hi;
    ((uint2*)g_xb)[i4] = packed;
}

// ---------------------------------------------------------------------------
// Kernel 1: sim = Xb * Xb^T via mma.sync.m16n8k16 bf16, fp32 accum, bf16 out.
// CTA tile 128(M) x 64(N) x 32(K); 8 warps (4 x 2), each 32x32.
// ---------------------------------------------------------------------------
#define BM 128
#define BN 64
#define BKg 32
#define BKP 40   // padded row length (bf16 units): 80B row -> conflict-free frag LDS

__device__ __forceinline__ void mma_bf16(float* c, const unsigned* a, const unsigned* b)
{
    asm volatile(
        "mma.sync.aligned.m16n8k16.row.col.f32.bf16.bf16.f32 "
        "{%0,%1,%2,%3}, {%4,%5,%6,%7}, {%8,%9}, {%0,%1,%2,%3};\n"
        : "+f"(c[0]), "+f"(c[1]), "+f"(c[2]), "+f"(c[3])
        : "r"(a[0]), "r"(a[1]), "r"(a[2]), "r"(a[3]), "r"(b[0]), "r"(b[1]));
}

__global__ __launch_bounds__(256) void gemm_bf16_kernel()
{
    __shared__ __align__(16) __nv_bfloat16 As[2][BM * BKP];
    __shared__ __align__(16) __nv_bfloat16 Bs[2][BN * BKP];

    const int tid  = threadIdx.x;
    const int lane = tid & 31;
    const int wid  = tid >> 5;
    const int wm   = wid & 3;     // 0..3 -> rows wm*32
    const int wn   = wid >> 2;    // 0..1 -> cols wn*32
    const int g    = lane >> 2;   // 0..7
    const int t    = lane & 3;    // 0..3

    const int mbase = blockIdx.y * BM;
    const int nbase = blockIdx.x * BN;

    // staging: A needs 512 uint4 (2/thread), B needs 256 uint4 (1/thread)
    const int arow = tid >> 2;            // 0..63 ; second chunk adds +64
    const int ako  = (tid & 3) * 8;       // bf16 offset within 32-wide k slab
    const int brow = tid >> 2;
    const int bko  = (tid & 3) * 8;

    float acc[2][4][4];
#pragma unroll
    for (int tm = 0; tm < 2; tm++)
#pragma unroll
        for (int tn = 0; tn < 4; tn++)
#pragma unroll
            for (int i = 0; i < 4; i++) acc[tm][tn][i] = 0.0f;

    // preload tile 0
    {
        uint4 a0 = *(const uint4*)(g_xb + (size_t)(mbase + arow) * D + ako);
        uint4 a1 = *(const uint4*)(g_xb + (size_t)(mbase + arow + 64) * D + ako);
        uint4 b0 = *(const uint4*)(g_xb + (size_t)(nbase + brow) * D + bko);
        *(uint4*)&As[0][arow * BKP + ako]        = a0;
        *(uint4*)&As[0][(arow + 64) * BKP + ako] = a1;
        *(uint4*)&Bs[0][brow * BKP + bko]        = b0;
    }
    __syncthreads();

    const int NT = D / BKg;  // 16
    for (int kt = 0; kt < NT; kt++) {
        const int cur = kt & 1, nxt = cur ^ 1;

        uint4 pa0, pa1, pb0;
        if (kt + 1 < NT) {
            const int kk = (kt + 1) * BKg;
            pa0 = *(const uint4*)(g_xb + (size_t)(mbase + arow) * D + kk + ako);
            pa1 = *(const uint4*)(g_xb + (size_t)(mbase + arow + 64) * D + kk + ako);
            pb0 = *(const uint4*)(g_xb + (size_t)(nbase + brow) * D + kk + bko);
        }

        // compute on cur
#pragma unroll
        for (int s = 0; s < 2; s++) {
            const int kb = s * 16;
            unsigned af[2][4], bfr[4][2];
#pragma unroll
            for (int tm = 0; tm < 2; tm++) {
                const int r = wm * 32 + tm * 16 + g;
                const __nv_bfloat16* ap = &As[cur][r * BKP + kb + t * 2];
                af[tm][0] = *(const unsigned*)ap;                 // (g, k)
                af[tm][1] = *(const unsigned*)(ap + 8 * BKP);     // (g+8, k)
                af[tm][2] = *(const unsigned*)(ap + 8);           // (g, k+8)
                af[tm][3] = *(const unsigned*)(ap + 8 * BKP + 8); // (g+8, k+8)
            }
#pragma unroll
            for (int tn = 0; tn < 4; tn++) {
                const int n = wn * 32 + tn * 8 + g;
                const __nv_bfloat16* bp = &Bs[cur][n * BKP + kb + t * 2];
                bfr[tn][0] = *(const unsigned*)bp;
                bfr[tn][1] = *(const unsigned*)(bp + 8);
            }
#pragma unroll
            for (int tm = 0; tm < 2; tm++)
#pragma unroll
                for (int tn = 0; tn < 4; tn++)
                    mma_bf16(acc[tm][tn], af[tm], bfr[tn]);
        }

        if (kt + 1 < NT) {
            *(uint4*)&As[nxt][arow * BKP + ako]        = pa0;
            *(uint4*)&As[nxt][(arow + 64) * BKP + ako] = pa1;
            *(uint4*)&Bs[nxt][brow * BKP + bko]        = pb0;
        }
        __syncthreads();
    }

    // epilogue: store bf16 sim
#pragma unroll
    for (int tm = 0; tm < 2; tm++) {
#pragma unroll
        for (int tn = 0; tn < 4; tn++) {
            const int r0 = mbase + wm * 32 + tm * 16 + g;
            const int c  = nbase + wn * 32 + tn * 8 + t * 2;
            __nv_bfloat162 v01 = __floats2bfloat162_rn(acc[tm][tn][0], acc[tm][tn][1]);
            __nv_bfloat162 v23 = __floats2bfloat162_rn(acc[tm][tn][2], acc[tm][tn][3]);
            *(__nv_bfloat162*)&g_sim[(size_t)r0 * N + c]       = v01;
            *(__nv_bfloat162*)&g_sim[(size_t)(r0 + 8) * N + c] = v23;
        }
    }
}

// ---------------------------------------------------------------------------
// Kernel 2: per-row top-32 candidate selection from bf16 sim.
// 256 threads / row; iterative argmax with shuffle + cross-warp reduction;
// only the owner thread rescans its strided chunk after each extraction.
// ---------------------------------------------------------------------------
__global__ __launch_bounds__(256) void select_cand_kernel()
{
    __shared__ float vals[N];          // 32 KB
    __shared__ float wv[8];
    __shared__ int   wi[8];
    __shared__ int   sGi;

    const int row  = blockIdx.x;
    const int tid  = threadIdx.x;
    const int lane = tid & 31;
    const int wid  = tid >> 5;

    const __nv_bfloat16* rowp = g_sim + (size_t)row * N;

    // load + convert row
    for (int j = tid; j < N / 4; j += 256) {
        uint2 p = ((const uint2*)rowp)[j];
        __nv_bfloat162 lo = *(__nv_bfloat162*)&p.x;
        __nv_bfloat162 hi = *(__nv_bfloat162*)&p.y;
        vals[j * 4 + 0] = __bfloat162float(lo.x);
        vals[j * 4 + 1] = __bfloat162float(lo.y);
        vals[j * 4 + 2] = __bfloat162float(hi.x);
        vals[j * 4 + 3] = __bfloat162float(hi.y);
    }
    __syncthreads();

    // local max over strided chunk j = tid + 256*t
    float bv = -INFINITY;
    int   bi = tid;
#pragma unroll 4
    for (int tt = 0; tt < N / 256; tt++) {
        int j = tid + tt * 256;
        float v = vals[j];
        if (v > bv) { bv = v; bi = j; }
    }

    for (int round = 0; round < NCAND; round++) {
        // warp argmax (value desc, index asc on tie)
        float v = bv;
        int   i = bi;
#pragma unroll
        for (int off = 16; off > 0; off >>= 1) {
            float ov = __shfl_down_sync(0xffffffff, v, off);
            int   oi = __shfl_down_sync(0xffffffff, i, off);
            if (ov > v || (ov == v && oi < i)) { v = ov; i = oi; }
        }
        if (lane == 0) { wv[wid] = v; wi[wid] = i; }
        __syncthreads();
        if (tid == 0) {
            float gv = wv[0];
            int   gi = wi[0];
#pragma unroll
            for (int w = 1; w < 8; w++) {
                if (wv[w] > gv || (wv[w] == gv && wi[w] < gi)) { gv = wv[w]; gi = wi[w]; }
            }
            g_cand[row * NCAND + round] = gi;
            vals[gi] = -INFINITY;
            sGi = gi;
        }
        __syncthreads();
        const int gi = sGi;
        if ((gi & 255) == tid) {
            // owner rescans its chunk
            bv = -INFINITY;
            bi = tid;
#pragma unroll 4
            for (int tt = 0; tt < N / 256; tt++) {
                int j = tid + tt * 256;
                float v2 = vals[j];
                if (v2 > bv) { bv = v2; bi = j; }
            }
        }
        __syncthreads();
    }
}

// ---------------------------------------------------------------------------
// Kernel 3: exact fp32 rescore of 32 candidates, top-16, zero row, scatter.
// ---------------------------------------------------------------------------
__global__ __launch_bounds__(256) void rescore_kernel(const float* __restrict__ x,
                                                      float* __restrict__ adj)
{
    __shared__ float xr[D];
    __shared__ float cv[NCAND];
    __shared__ int   ci[NCAND];

    const int row  = blockIdx.x;
    const int tid  = threadIdx.x;
    const int lane = tid & 31;
    const int wid  = tid >> 5;

    // load x[row] into smem
    for (int k = tid; k < D; k += 256) xr[k] = x[(size_t)row * D + k];
    __syncthreads();

    // 8 warps x 4 candidates
#pragma unroll
    for (int j = 0; j < 4; j++) {
        const int c   = wid * 4 + j;
        const int col = g_cand[row * NCAND + c];
        const float* xc = x + (size_t)col * D;
        float sum = 0.0f;
#pragma unroll
        for (int k = lane; k < D; k += 32) sum = fmaf(xr[k], xc[k], sum);
#pragma unroll
        for (int off = 16; off > 0; off >>= 1)
            sum += __shfl_down_sync(0xffffffff, sum, off);
        if (lane == 0) { cv[c] = sum; ci[c] = col; }
    }
    __syncthreads();

    // zero the whole row
    float4* rp = (float4*)(adj + (size_t)row * N);
    const float4 z = make_float4(0.f, 0.f, 0.f, 0.f);
    for (int u = tid; u < N / 4; u += 256) rp[u] = z;
    __syncthreads();

    // rank candidates (value desc, column asc on tie) and scatter top-16
    if (tid < NCAND) {
        const float v   = cv[tid];
        const int   col = ci[tid];
        int rank = 0;
#pragma unroll
        for (int j2 = 0; j2 < NCAND; j2++) {
            float vj = cv[j2];
            int   cj = ci[j2];
            rank += (vj > v) || (vj == v && cj < col);
        }
        if (rank < KSEL) adj[(size_t)row * N + col] = v;
    }
}

// ---------------------------------------------------------------------------
// Launch
// ---------------------------------------------------------------------------
extern "C" void kernel_launch(void* const* d_in, const int* in_sizes, int n_in,
                              void* d_out, int out_size)
{
    const float* x = (const float*)d_in[0];
    float* out = (float*)d_out;

    float* out_x   = out;
    float* out_adj = out + (size_t)N * D;

    // pass-through copy of x
    cudaMemcpyAsync(out_x, x, (size_t)N * D * sizeof(float),
                    cudaMemcpyDeviceToDevice, 0);

    // 0) fp32 -> bf16
    convert_bf16_kernel<<<(N * D) / 1024, 256>>>(x);

    // 1) bf16 tensor-core GEMM -> g_sim
    dim3 grid(N / BN, N / BM);
    gemm_bf16_kernel<<<grid, 256>>>();

    // 2) per-row top-32 candidates
    select_cand_kernel<<<N, 256>>>();

    // 3) exact fp32 rescore + zero + scatter
    rescore_kernel<<<N, 256>>>(x, out_adj);
}

// round 6
// speedup vs baseline: 6.0613x; 1.3928x over previous
#include <cuda_runtime.h>
#include <cuda_bf16.h>
#include <math.h>
#include <stdint.h>

#define N 8192
#define D 512
#define KSEL 16
#define NCAND 32

// ---------------- static device scratch (no runtime allocation) -----------
__device__ __align__(16) __nv_bfloat16 g_xb[(size_t)N * D];        // 8 MB
__device__ __align__(16) __nv_bfloat16 g_sim[(size_t)N * N];       // 128 MB
__device__ int g_cand[N * NCAND];                                  // 1 MB

// ======================= helpers ==========================================
__device__ __forceinline__ uint32_t smem_u32(const void* p) {
    uint32_t a;
    asm("{ .reg .u64 t; cvta.to.shared.u64 t, %1; cvt.u32.u64 %0, t; }"
        : "=r"(a) : "l"(p));
    return a;
}
#define CP_ASYNC16(dst, src) \
    asm volatile("cp.async.cg.shared.global [%0], [%1], 16;" :: "r"(dst), "l"(src))
#define CP_ASYNC_COMMIT() asm volatile("cp.async.commit_group;" ::: "memory")
#define CP_ASYNC_WAIT1()  asm volatile("cp.async.wait_group 1;" ::: "memory")
#define CP_ASYNC_WAIT0()  asm volatile("cp.async.wait_group 0;" ::: "memory")

__device__ __forceinline__ void mma_bf16(float* c, const unsigned* a, const unsigned* b)
{
    asm volatile(
        "mma.sync.aligned.m16n8k16.row.col.f32.bf16.bf16.f32 "
        "{%0,%1,%2,%3}, {%4,%5,%6,%7}, {%8,%9}, {%0,%1,%2,%3};\n"
        : "+f"(c[0]), "+f"(c[1]), "+f"(c[2]), "+f"(c[3])
        : "r"(a[0]), "r"(a[1]), "r"(a[2]), "r"(a[3]), "r"(b[0]), "r"(b[1]));
}

// ---------------------------------------------------------------------------
// Kernel 0: convert x (fp32) -> bf16 scratch
// ---------------------------------------------------------------------------
__global__ __launch_bounds__(256) void convert_bf16_kernel(const float* __restrict__ x)
{
    int i4 = blockIdx.x * 256 + threadIdx.x;
    float4 v = ((const float4*)x)[i4];
    __nv_bfloat162 lo = __floats2bfloat162_rn(v.x, v.y);
    __nv_bfloat162 hi = __floats2bfloat162_rn(v.z, v.w);
    uint2 packed;
    packed.x = *(unsigned*)&lo;
    packed.y = *(unsigned*)&hi;
    ((uint2*)g_xb)[i4] = packed;
}

// ---------------------------------------------------------------------------
// Kernel 1: sim = Xb * Xb^T, symmetric: only tiles with bx >= by computed;
// off-diagonal tiles mirrored via smem transpose.
// CTA tile 128x128, BK=32, 3-stage cp.async pipeline, 8 warps (2x4), warp
// tile 64x32, mma.sync.m16n8k16 bf16.
// ---------------------------------------------------------------------------
#define BMg 128
#define BNg 128
#define BKg 32
#define BKP 40                          // padded k-stride (bf16 units), 80 B rows
#define STAGES 3
#define A_UNITS (BMg * BKP)             // 5120 bf16
#define B_UNITS (BNg * BKP)
#define STAGE_UNITS (A_UNITS + B_UNITS) // 10240 bf16 = 20480 B
#define PIPE_BYTES (STAGES * STAGE_UNITS * 2)   // 61440
#define TILE_LD 136                     // epilogue staging row stride (bf16)
#define EPI_BYTES (BMg * TILE_LD * 2)   // 34816
#define SMEM_GEMM (PIPE_BYTES > EPI_BYTES ? PIPE_BYTES : EPI_BYTES)

__device__ __forceinline__ void issue_stage(uint32_t sA, uint32_t sB,
                                            int mbase, int nbase, int k0, int tid)
{
#pragma unroll
    for (int i = 0; i < 2; i++) {
        int id  = tid + i * 256;         // 0..511
        int row = id >> 2;               // 0..127
        int c   = id & 3;                // 16B chunk within 64B row
        CP_ASYNC16(sA + row * 80 + c * 16,
                   g_xb + (size_t)(mbase + row) * D + k0 + c * 8);
        CP_ASYNC16(sB + row * 80 + c * 16,
                   g_xb + (size_t)(nbase + row) * D + k0 + c * 8);
    }
    CP_ASYNC_COMMIT();
}

__global__ __launch_bounds__(256) void gemm_sym_kernel()
{
    const int bx = blockIdx.x;   // n tile
    const int by = blockIdx.y;   // m tile
    if (by > bx) return;         // triangle only

    extern __shared__ __align__(16) char smem_raw[];
    __nv_bfloat16* smem = (__nv_bfloat16*)smem_raw;
    const uint32_t sb = smem_u32(smem);

    const int tid  = threadIdx.x;
    const int lane = tid & 31;
    const int wid  = tid >> 5;
    const int wm   = wid >> 2;      // 0..1 -> rows wm*64
    const int wn   = wid & 3;       // 0..3 -> cols wn*32
    const int g    = lane >> 2;     // 0..7
    const int t    = lane & 3;      // 0..3

    const int mbase = by * BMg;
    const int nbase = bx * BNg;

    float acc[4][4][4];
#pragma unroll
    for (int i = 0; i < 4; i++)
#pragma unroll
        for (int j = 0; j < 4; j++)
#pragma unroll
            for (int q = 0; q < 4; q++) acc[i][j][q] = 0.0f;

    // prologue: stages 0..STAGES-2
#pragma unroll
    for (int s = 0; s < STAGES - 1; s++) {
        uint32_t base = sb + s * STAGE_UNITS * 2;
        issue_stage(base, base + A_UNITS * 2, mbase, nbase, s * BKg, tid);
    }

    const int NT = D / BKg;   // 16
    for (int kt = 0; kt < NT; kt++) {
        CP_ASYNC_WAIT1();
        __syncthreads();

        // prefetch next stage (safe: all warps finished reading it last iter)
        const int nk = kt + STAGES - 1;
        if (nk < NT) {
            uint32_t base = sb + (nk % STAGES) * STAGE_UNITS * 2;
            issue_stage(base, base + A_UNITS * 2, mbase, nbase, nk * BKg, tid);
        }

        const __nv_bfloat16* As = smem + (kt % STAGES) * STAGE_UNITS;
        const __nv_bfloat16* Bs = As + A_UNITS;

#pragma unroll
        for (int s = 0; s < 2; s++) {
            const int kb = s * 16;
            unsigned af[4][4], bfr[4][2];
#pragma unroll
            for (int i = 0; i < 4; i++) {
                const int r = wm * 64 + i * 16 + g;
                const __nv_bfloat16* ap = &As[r * BKP + kb + t * 2];
                af[i][0] = *(const unsigned*)ap;
                af[i][1] = *(const unsigned*)(ap + 8 * BKP);
                af[i][2] = *(const unsigned*)(ap + 8);
                af[i][3] = *(const unsigned*)(ap + 8 * BKP + 8);
            }
#pragma unroll
            for (int j = 0; j < 4; j++) {
                const int n = wn * 32 + j * 8 + g;
                const __nv_bfloat16* bp = &Bs[n * BKP + kb + t * 2];
                bfr[j][0] = *(const unsigned*)bp;
                bfr[j][1] = *(const unsigned*)(bp + 8);
            }
#pragma unroll
            for (int i = 0; i < 4; i++)
#pragma unroll
                for (int j = 0; j < 4; j++)
                    mma_bf16(acc[i][j], af[i], bfr[j]);
        }
    }
    CP_ASYNC_WAIT0();
    __syncthreads();   // done with pipeline smem; reuse for epilogue staging

    // ---- stage bf16 tile in smem: tile[row][col], row stride TILE_LD ----
    __nv_bfloat16* tile = smem;
#pragma unroll
    for (int i = 0; i < 4; i++) {
#pragma unroll
        for (int j = 0; j < 4; j++) {
            const int r0 = wm * 64 + i * 16 + g;
            const int c  = wn * 32 + j * 8 + t * 2;
            __nv_bfloat162 v01 = __floats2bfloat162_rn(acc[i][j][0], acc[i][j][1]);
            __nv_bfloat162 v23 = __floats2bfloat162_rn(acc[i][j][2], acc[i][j][3]);
            *(__nv_bfloat162*)&tile[r0 * TILE_LD + c]       = v01;
            *(__nv_bfloat162*)&tile[(r0 + 8) * TILE_LD + c] = v23;
        }
    }
    __syncthreads();

    // ---- direct write: C[mbase..][nbase..] (vectorized rows) ----
#pragma unroll
    for (int kk = 0; kk < 8; kk++) {
        int u   = tid + kk * 256;       // 0..2047
        int row = u >> 4;               // 0..127
        int seg = u & 15;               // 16B segment
        *(uint4*)(g_sim + (size_t)(mbase + row) * N + nbase + seg * 8) =
            *(const uint4*)&tile[row * TILE_LD + seg * 8];
    }

    // ---- mirror write: C[nbase..][mbase..] = tile^T ----
    if (bx != by) {
        const int c = tid & 127;        // column of tile == row offset of mirror
        const int h = tid >> 7;         // 0/1 -> m-half
        __nv_bfloat16* dst = g_sim + (size_t)(nbase + c) * N + mbase + h * 64;
#pragma unroll
        for (int qq = 0; qq < 8; qq++) {
            uint32_t w[4];
#pragma unroll
            for (int p = 0; p < 2; p++) {
                int r = h * 64 + qq * 8 + p * 4;
                __nv_bfloat162 a, b;
                a.x = tile[(r + 0) * TILE_LD + c];
                a.y = tile[(r + 1) * TILE_LD + c];
                b.x = tile[(r + 2) * TILE_LD + c];
                b.y = tile[(r + 3) * TILE_LD + c];
                w[2 * p]     = *(uint32_t*)&a;
                w[2 * p + 1] = *(uint32_t*)&b;
            }
            *(uint4*)(dst + qq * 8) = make_uint4(w[0], w[1], w[2], w[3]);
        }
    }
}

// ---------------------------------------------------------------------------
// Kernel 2: per-row top-32 candidate selection from bf16 sim.
// ---------------------------------------------------------------------------
__global__ __launch_bounds__(256) void select_cand_kernel()
{
    __shared__ float vals[N];
    __shared__ float wv[8];
    __shared__ int   wi[8];
    __shared__ int   sGi;

    const int row  = blockIdx.x;
    const int tid  = threadIdx.x;
    const int lane = tid & 31;
    const int wid  = tid >> 5;

    const __nv_bfloat16* rowp = g_sim + (size_t)row * N;
    for (int j = tid; j < N / 4; j += 256) {
        uint2 p = ((const uint2*)rowp)[j];
        __nv_bfloat162 lo = *(__nv_bfloat162*)&p.x;
        __nv_bfloat162 hi = *(__nv_bfloat162*)&p.y;
        vals[j * 4 + 0] = __bfloat162float(lo.x);
        vals[j * 4 + 1] = __bfloat162float(lo.y);
        vals[j * 4 + 2] = __bfloat162float(hi.x);
        vals[j * 4 + 3] = __bfloat162float(hi.y);
    }
    __syncthreads();

    float bv = -INFINITY;
    int   bi = tid;
#pragma unroll 4
    for (int tt = 0; tt < N / 256; tt++) {
        int j = tid + tt * 256;
        float v = vals[j];
        if (v > bv) { bv = v; bi = j; }
    }

    for (int round = 0; round < NCAND; round++) {
        float v = bv;
        int   i = bi;
#pragma unroll
        for (int off = 16; off > 0; off >>= 1) {
            float ov = __shfl_down_sync(0xffffffff, v, off);
            int   oi = __shfl_down_sync(0xffffffff, i, off);
            if (ov > v || (ov == v && oi < i)) { v = ov; i = oi; }
        }
        if (lane == 0) { wv[wid] = v; wi[wid] = i; }
        __syncthreads();
        if (tid == 0) {
            float gv = wv[0];
            int   gi = wi[0];
#pragma unroll
            for (int w = 1; w < 8; w++)
                if (wv[w] > gv || (wv[w] == gv && wi[w] < gi)) { gv = wv[w]; gi = wi[w]; }
            g_cand[row * NCAND + round] = gi;
            vals[gi] = -INFINITY;
            sGi = gi;
        }
        __syncthreads();
        const int gi = sGi;
        if ((gi & 255) == tid) {
            bv = -INFINITY;
            bi = tid;
#pragma unroll 4
            for (int tt = 0; tt < N / 256; tt++) {
                int j = tid + tt * 256;
                float v2 = vals[j];
                if (v2 > bv) { bv = v2; bi = j; }
            }
        }
        __syncthreads();
    }
}

// ---------------------------------------------------------------------------
// Kernel 3: exact fp32 rescore of 32 candidates, top-16, zero row, scatter.
// ---------------------------------------------------------------------------
__global__ __launch_bounds__(256) void rescore_kernel(const float* __restrict__ x,
                                                      float* __restrict__ adj)
{
    __shared__ float xr[D];
    __shared__ float cv[NCAND];
    __shared__ int   ci[NCAND];

    const int row  = blockIdx.x;
    const int tid  = threadIdx.x;
    const int lane = tid & 31;
    const int wid  = tid >> 5;

    for (int k = tid; k < D; k += 256) xr[k] = x[(size_t)row * D + k];
    __syncthreads();

#pragma unroll
    for (int j = 0; j < 4; j++) {
        const int c   = wid * 4 + j;
        const int col = g_cand[row * NCAND + c];
        const float* xc = x + (size_t)col * D;
        float sum = 0.0f;
#pragma unroll
        for (int k = lane; k < D; k += 32) sum = fmaf(xr[k], xc[k], sum);
#pragma unroll
        for (int off = 16; off > 0; off >>= 1)
            sum += __shfl_down_sync(0xffffffff, sum, off);
        if (lane == 0) { cv[c] = sum; ci[c] = col; }
    }
    __syncthreads();

    float4* rp = (float4*)(adj + (size_t)row * N);
    const float4 z = make_float4(0.f, 0.f, 0.f, 0.f);
    for (int u = tid; u < N / 4; u += 256) rp[u] = z;
    __syncthreads();

    if (tid < NCAND) {
        const float v   = cv[tid];
        const int   col = ci[tid];
        int rank = 0;
#pragma unroll
        for (int j2 = 0; j2 < NCAND; j2++) {
            float vj = cv[j2];
            int   cj = ci[j2];
            rank += (vj > v) || (vj == v && cj < col);
        }
        if (rank < KSEL) adj[(size_t)row * N + col] = v;
    }
}

// ---------------------------------------------------------------------------
// Launch
// ---------------------------------------------------------------------------
extern "C" void kernel_launch(void* const* d_in, const int* in_sizes, int n_in,
                              void* d_out, int out_size)
{
    const float* x = (const float*)d_in[0];
    float* out = (float*)d_out;

    float* out_x   = out;
    float* out_adj = out + (size_t)N * D;

    cudaMemcpyAsync(out_x, x, (size_t)N * D * sizeof(float),
                    cudaMemcpyDeviceToDevice, 0);

    convert_bf16_kernel<<<(N * D) / 1024, 256>>>(x);

    cudaFuncSetAttribute(gemm_sym_kernel,
                         cudaFuncAttributeMaxDynamicSharedMemorySize, SMEM_GEMM);
    dim3 grid(N / BNg, N / BMg);   // 64 x 64, upper triangle computes
    gemm_sym_kernel<<<grid, 256, SMEM_GEMM>>>();

    select_cand_kernel<<<N, 256>>>();

    rescore_kernel<<<N, 256>>>(x, out_adj);
}

// round 8
// speedup vs baseline: 6.0900x; 1.0047x over previous
#include <cuda_runtime.h>
#include <cuda_bf16.h>
#include <math.h>
#include <stdint.h>

#define N 8192
#define D 512
#define KSEL 16
#define CCAP 64            // candidate capacity per row

// ---------------- static device scratch (no runtime allocation) -----------
__device__ __align__(16) __nv_bfloat16 g_xb[(size_t)N * D];        // 8 MB
__device__ __align__(16) __nv_bfloat16 g_sim[(size_t)N * N];       // 128 MB
__device__ int g_cand[N * CCAP];                                   // 2 MB
__device__ int g_cnt[N];

// ======================= helpers ==========================================
__device__ __forceinline__ uint32_t smem_u32(const void* p) {
    uint32_t a;
    asm("{ .reg .u64 t; cvta.to.shared.u64 t, %1; cvt.u32.u64 %0, t; }"
        : "=r"(a) : "l"(p));
    return a;
}
#define CP_ASYNC16(dst, src) \
    asm volatile("cp.async.cg.shared.global [%0], [%1], 16;" :: "r"(dst), "l"(src))
#define CP_ASYNC_COMMIT() asm volatile("cp.async.commit_group;" ::: "memory")
#define CP_ASYNC_WAIT1()  asm volatile("cp.async.wait_group 1;" ::: "memory")
#define CP_ASYNC_WAIT0()  asm volatile("cp.async.wait_group 0;" ::: "memory")

#define LDSM_X4(r0, r1, r2, r3, addr)                                        \
    asm volatile("ldmatrix.sync.aligned.m8n8.x4.shared.b16 {%0,%1,%2,%3}, [%4];" \
                 : "=r"(r0), "=r"(r1), "=r"(r2), "=r"(r3) : "r"(addr))
#define LDSM_X2(r0, r1, addr)                                                \
    asm volatile("ldmatrix.sync.aligned.m8n8.x2.shared.b16 {%0,%1}, [%2];"   \
                 : "=r"(r0), "=r"(r1) : "r"(addr))

__device__ __forceinline__ void mma_bf16(float* c, const unsigned* a, const unsigned* b)
{
    asm volatile(
        "mma.sync.aligned.m16n8k16.row.col.f32.bf16.bf16.f32 "
        "{%0,%1,%2,%3}, {%4,%5,%6,%7}, {%8,%9}, {%0,%1,%2,%3};\n"
        : "+f"(c[0]), "+f"(c[1]), "+f"(c[2]), "+f"(c[3])
        : "r"(a[0]), "r"(a[1]), "r"(a[2]), "r"(a[3]), "r"(b[0]), "r"(b[1]));
}

// ---------------------------------------------------------------------------
// Kernel 0: convert x (fp32) -> bf16 scratch
// ---------------------------------------------------------------------------
__global__ __launch_bounds__(256) void convert_bf16_kernel(const float* __restrict__ x)
{
    int i4 = blockIdx.x * 256 + threadIdx.x;
    float4 v = ((const float4*)x)[i4];
    __nv_bfloat162 lo = __floats2bfloat162_rn(v.x, v.y);
    __nv_bfloat162 hi = __floats2bfloat162_rn(v.z, v.w);
    uint2 packed;
    packed.x = *(unsigned*)&lo;
    packed.y = *(unsigned*)&hi;
    ((uint2*)g_xb)[i4] = packed;
}

// ---------------------------------------------------------------------------
// Kernel 1: sim = Xb * Xb^T, symmetric (bx >= by), ldmatrix fragment loads.
// 3-stage cp.async pipeline with a commit EVERY iteration (empty commits in
// the tail) so wait_group 1 always guarantees the consumed stage is complete.
// ---------------------------------------------------------------------------
#define BMg 128
#define BNg 128
#define BKg 32
#define BKP 40
#define STAGES 3
#define A_UNITS (BMg * BKP)
#define B_UNITS (BNg * BKP)
#define STAGE_UNITS (A_UNITS + B_UNITS)
#define PIPE_BYTES (STAGES * STAGE_UNITS * 2)
#define TILE_LD 136
#define EPI_BYTES (BMg * TILE_LD * 2)
#define SMEM_GEMM (PIPE_BYTES > EPI_BYTES ? PIPE_BYTES : EPI_BYTES)

__device__ __forceinline__ void issue_stage(uint32_t sA, uint32_t sB,
                                            int mbase, int nbase, int k0, int tid)
{
#pragma unroll
    for (int i = 0; i < 2; i++) {
        int id  = tid + i * 256;
        int row = id >> 2;
        int c   = id & 3;
        CP_ASYNC16(sA + row * 80 + c * 16,
                   g_xb + (size_t)(mbase + row) * D + k0 + c * 8);
        CP_ASYNC16(sB + row * 80 + c * 16,
                   g_xb + (size_t)(nbase + row) * D + k0 + c * 8);
    }
    CP_ASYNC_COMMIT();
}

__global__ __launch_bounds__(256) void gemm_sym_kernel()
{
    const int bx = blockIdx.x;
    const int by = blockIdx.y;
    if (by > bx) return;

    extern __shared__ __align__(16) char smem_raw[];
    __nv_bfloat16* smem = (__nv_bfloat16*)smem_raw;
    const uint32_t sb = smem_u32(smem);

    const int tid  = threadIdx.x;
    const int lane = tid & 31;
    const int wid  = tid >> 5;
    const int wm   = wid >> 2;
    const int wn   = wid & 3;
    const int g    = lane >> 2;
    const int t    = lane & 3;

    const int mbase = by * BMg;
    const int nbase = bx * BNg;

    // per-lane ldmatrix address offsets (bytes)
    const uint32_t aLaneOff = ((lane & 15) * BKP + (lane >> 4) * 8) * 2 +
                              (wm * 64) * BKP * 2;
    const uint32_t bLaneOff = ((lane & 7) * BKP + ((lane >> 3) & 1) * 8) * 2 +
                              (wn * 32) * BKP * 2;

    float acc[4][4][4];
#pragma unroll
    for (int i = 0; i < 4; i++)
#pragma unroll
        for (int j = 0; j < 4; j++)
#pragma unroll
            for (int q = 0; q < 4; q++) acc[i][j][q] = 0.0f;

#pragma unroll
    for (int s = 0; s < STAGES - 1; s++) {
        uint32_t base = sb + s * STAGE_UNITS * 2;
        issue_stage(base, base + A_UNITS * 2, mbase, nbase, s * BKg, tid);
    }

    const int NT = D / BKg;
    for (int kt = 0; kt < NT; kt++) {
        CP_ASYNC_WAIT1();
        __syncthreads();

        const int nk = kt + STAGES - 1;
        if (nk < NT) {
            uint32_t base = sb + (nk % STAGES) * STAGE_UNITS * 2;
            issue_stage(base, base + A_UNITS * 2, mbase, nbase, nk * BKg, tid);
        } else {
            // EMPTY commit keeps wait_group semantics sound in the tail:
            // without it, wait_group 1 can leave the final real stage in
            // flight while it is being consumed.
            CP_ASYNC_COMMIT();
        }

        const uint32_t sA = sb + (kt % STAGES) * STAGE_UNITS * 2;
        const uint32_t sB = sA + A_UNITS * 2;
        const uint32_t aBase = sA + aLaneOff;
        const uint32_t bBase = sB + bLaneOff;

#pragma unroll
        for (int s = 0; s < 2; s++) {
            const uint32_t kOff = s * 32;   // 16 bf16 = 32 B
            unsigned af[4][4], bfr[4][2];
#pragma unroll
            for (int i = 0; i < 4; i++)
                LDSM_X4(af[i][0], af[i][1], af[i][2], af[i][3],
                        aBase + i * (16 * BKP * 2) + kOff);
#pragma unroll
            for (int j = 0; j < 4; j++)
                LDSM_X2(bfr[j][0], bfr[j][1],
                        bBase + j * (8 * BKP * 2) + kOff);
#pragma unroll
            for (int i = 0; i < 4; i++)
#pragma unroll
                for (int j = 0; j < 4; j++)
                    mma_bf16(acc[i][j], af[i], bfr[j]);
        }
    }
    CP_ASYNC_WAIT0();
    __syncthreads();

    // stage bf16 tile in smem
    __nv_bfloat16* tile = smem;
#pragma unroll
    for (int i = 0; i < 4; i++) {
#pragma unroll
        for (int j = 0; j < 4; j++) {
            const int r0 = wm * 64 + i * 16 + g;
            const int c  = wn * 32 + j * 8 + t * 2;
            __nv_bfloat162 v01 = __floats2bfloat162_rn(acc[i][j][0], acc[i][j][1]);
            __nv_bfloat162 v23 = __floats2bfloat162_rn(acc[i][j][2], acc[i][j][3]);
            *(__nv_bfloat162*)&tile[r0 * TILE_LD + c]       = v01;
            *(__nv_bfloat162*)&tile[(r0 + 8) * TILE_LD + c] = v23;
        }
    }
    __syncthreads();

    // direct write
#pragma unroll
    for (int kk = 0; kk < 8; kk++) {
        int u   = tid + kk * 256;
        int row = u >> 4;
        int seg = u & 15;
        *(uint4*)(g_sim + (size_t)(mbase + row) * N + nbase + seg * 8) =
            *(const uint4*)&tile[row * TILE_LD + seg * 8];
    }

    // mirror write
    if (bx != by) {
        const int c = tid & 127;
        const int h = tid >> 7;
        __nv_bfloat16* dst = g_sim + (size_t)(nbase + c) * N + mbase + h * 64;
#pragma unroll
        for (int qq = 0; qq < 8; qq++) {
            uint32_t w[4];
#pragma unroll
            for (int p = 0; p < 2; p++) {
                int r = h * 64 + qq * 8 + p * 4;
                __nv_bfloat162 a, b;
                a.x = tile[(r + 0) * TILE_LD + c];
                a.y = tile[(r + 1) * TILE_LD + c];
                b.x = tile[(r + 2) * TILE_LD + c];
                b.y = tile[(r + 3) * TILE_LD + c];
                w[2 * p]     = *(uint32_t*)&a;
                w[2 * p + 1] = *(uint32_t*)&b;
            }
            *(uint4*)(dst + qq * 8) = make_uint4(w[0], w[1], w[2], w[3]);
        }
    }
}

// ---------------------------------------------------------------------------
// Kernel 2: histogram-threshold candidate selection.
// Monotonic 16-bit key from bf16 bits; 8192-bin histogram (key >> 3);
// suffix scan to the bin where cumulative-from-top >= 32; collect all >= bin.
// ---------------------------------------------------------------------------
__global__ __launch_bounds__(256) void select_hist_kernel()
{
    __shared__ uint32_t rowbuf[N / 2];      // 16 KB: bf16 row as 4096 u32
    __shared__ uint32_t hist[8192];         // 32 KB
    __shared__ int chunkS[256];
    __shared__ int sB, sCnt, sIdx;

    const int row = blockIdx.x;
    const int tid = threadIdx.x;

    // zero histogram
#pragma unroll
    for (int i = 0; i < 32; i++) hist[tid + i * 256] = 0;

    // load row (coalesced uint4)
    const uint4* src = (const uint4*)(g_sim + (size_t)row * N);
#pragma unroll
    for (int i = 0; i < 4; i++)
        ((uint4*)rowbuf)[tid + i * 256] = src[tid + i * 256];
    __syncthreads();

    // pass 1: histogram of 13-bit keys
#pragma unroll
    for (int i = 0; i < 16; i++) {
        uint32_t w = rowbuf[tid + i * 256];
        uint32_t lo = w & 0xFFFFu, hi = w >> 16;
        uint32_t klo = lo ^ ((lo & 0x8000u) ? 0xFFFFu : 0x8000u);
        uint32_t khi = hi ^ ((hi & 0x8000u) ? 0xFFFFu : 0x8000u);
        atomicAdd(&hist[klo >> 3], 1u);
        atomicAdd(&hist[khi >> 3], 1u);
    }
    __syncthreads();

    // chunk sums (32 bins per thread)
    {
        int s = 0;
        const int b0 = tid * 32;
#pragma unroll
        for (int b = 0; b < 32; b++) s += (int)hist[b0 + b];
        chunkS[tid] = s;
    }
    if (tid == 0) sIdx = 0;
    __syncthreads();

    // serial suffix scan (bounded: values concentrated in top chunks)
    if (tid == 0) {
        int cum = 0, Bbin = 0;
        for (int c = 255; c >= 0; c--) {
            int cs = chunkS[c];
            if (cum + cs >= 32 && cs > 0) {
                for (int b = c * 32 + 31; b >= c * 32; b--) {
                    cum += (int)hist[b];
                    if (cum >= 32) { Bbin = b; break; }
                }
                if (cum >= 32) break;
            } else {
                cum += cs;
            }
        }
        sB = Bbin;
        sCnt = cum;
    }
    __syncthreads();
    const uint32_t B = (uint32_t)sB;

    // pass 2: collect all with bin >= B
#pragma unroll
    for (int i = 0; i < 16; i++) {
        const int u = tid + i * 256;
        uint32_t w = rowbuf[u];
        uint32_t lo = w & 0xFFFFu, hi = w >> 16;
        uint32_t klo = lo ^ ((lo & 0x8000u) ? 0xFFFFu : 0x8000u);
        uint32_t khi = hi ^ ((hi & 0x8000u) ? 0xFFFFu : 0x8000u);
        if ((klo >> 3) >= B) {
            int slot = atomicAdd(&sIdx, 1);
            if (slot < CCAP) g_cand[row * CCAP + slot] = 2 * u;
        }
        if ((khi >> 3) >= B) {
            int slot = atomicAdd(&sIdx, 1);
            if (slot < CCAP) g_cand[row * CCAP + slot] = 2 * u + 1;
        }
    }
    __syncthreads();
    if (tid == 0) g_cnt[row] = (sCnt < CCAP) ? sCnt : CCAP;
}

// ---------------------------------------------------------------------------
// Kernel 3: exact fp32 rescore of cnt candidates, top-16, zero row, scatter.
// ---------------------------------------------------------------------------
__global__ __launch_bounds__(256) void rescore_kernel(const float* __restrict__ x,
                                                      float* __restrict__ adj)
{
    __shared__ float xr[D];
    __shared__ float cv[CCAP];
    __shared__ int   ci[CCAP];

    const int row  = blockIdx.x;
    const int tid  = threadIdx.x;
    const int lane = tid & 31;
    const int wid  = tid >> 5;

    const int cnt = g_cnt[row];

    if (tid < CCAP) { cv[tid] = -INFINITY; ci[tid] = -1; }
    for (int k = tid; k < D; k += 256) xr[k] = x[(size_t)row * D + k];
    __syncthreads();

#pragma unroll
    for (int j = 0; j < CCAP / 8; j++) {
        const int c = wid + j * 8;
        if (c < cnt) {
            const int col = g_cand[row * CCAP + c];
            const float* xc = x + (size_t)col * D;
            float sum = 0.0f;
#pragma unroll
            for (int k = lane; k < D; k += 32) sum = fmaf(xr[k], xc[k], sum);
#pragma unroll
            for (int off = 16; off > 0; off >>= 1)
                sum += __shfl_down_sync(0xffffffff, sum, off);
            if (lane == 0) { cv[c] = sum; ci[c] = col; }
        }
    }
    __syncthreads();

    // zero the whole row
    float4* rp = (float4*)(adj + (size_t)row * N);
    const float4 z = make_float4(0.f, 0.f, 0.f, 0.f);
    for (int u = tid; u < N / 4; u += 256) rp[u] = z;
    __syncthreads();

    // rank (value desc, col asc on tie) and scatter top-16
    if (tid < cnt) {
        const float v   = cv[tid];
        const int   col = ci[tid];
        int rank = 0;
#pragma unroll
        for (int j2 = 0; j2 < CCAP; j2++) {
            float vj = cv[j2];
            int   cj = ci[j2];
            rank += (vj > v) || (vj == v && cj < col);
        }
        if (rank < KSEL) adj[(size_t)row * N + col] = v;
    }
}

// ---------------------------------------------------------------------------
// Launch
// ---------------------------------------------------------------------------
extern "C" void kernel_launch(void* const* d_in, const int* in_sizes, int n_in,
                              void* d_out, int out_size)
{
    const float* x = (const float*)d_in[0];
    float* out = (float*)d_out;

    float* out_x   = out;
    float* out_adj = out + (size_t)N * D;

    cudaMemcpyAsync(out_x, x, (size_t)N * D * sizeof(float),
                    cudaMemcpyDeviceToDevice, 0);

    convert_bf16_kernel<<<(N * D) / 1024, 256>>>(x);

    cudaFuncSetAttribute(gemm_sym_kernel,
                         cudaFuncAttributeMaxDynamicSharedMemorySize, SMEM_GEMM);
    dim3 grid(N / BNg, N / BMg);
    gemm_sym_kernel<<<grid, 256, SMEM_GEMM>>>();

    select_hist_kernel<<<N, 256>>>();

    rescore_kernel<<<N, 256>>>(x, out_adj);
}

// round 9
// speedup vs baseline: 6.5529x; 1.0760x over previous
#include <cuda_runtime.h>
#include <cuda_bf16.h>
#include <math.h>
#include <stdint.h>

#define N 8192
#define D 512
#define KSEL 16
#define CCAP 64            // candidate capacity per row

// ---------------- static device scratch (no runtime allocation) -----------
__device__ __align__(16) __nv_bfloat16 g_xb[(size_t)N * D];        // 8 MB
__device__ __align__(16) __nv_bfloat16 g_sim[(size_t)N * N];       // 128 MB
__device__ int g_cand[N * CCAP];                                   // 2 MB
__device__ int g_cnt[N];

// ======================= helpers ==========================================
__device__ __forceinline__ uint32_t smem_u32(const void* p) {
    uint32_t a;
    asm("{ .reg .u64 t; cvta.to.shared.u64 t, %1; cvt.u32.u64 %0, t; }"
        : "=r"(a) : "l"(p));
    return a;
}
#define CP_ASYNC16(dst, src) \
    asm volatile("cp.async.cg.shared.global [%0], [%1], 16;" :: "r"(dst), "l"(src))
#define CP_ASYNC_COMMIT() asm volatile("cp.async.commit_group;" ::: "memory")
#define CP_ASYNC_WAIT1()  asm volatile("cp.async.wait_group 1;" ::: "memory")
#define CP_ASYNC_WAIT0()  asm volatile("cp.async.wait_group 0;" ::: "memory")

#define LDSM_X4(r0, r1, r2, r3, addr)                                        \
    asm volatile("ldmatrix.sync.aligned.m8n8.x4.shared.b16 {%0,%1,%2,%3}, [%4];" \
                 : "=r"(r0), "=r"(r1), "=r"(r2), "=r"(r3) : "r"(addr))
#define LDSM_X2(r0, r1, addr)                                                \
    asm volatile("ldmatrix.sync.aligned.m8n8.x2.shared.b16 {%0,%1}, [%2];"   \
                 : "=r"(r0), "=r"(r1) : "r"(addr))

__device__ __forceinline__ void mma_bf16(float* c, const unsigned* a, const unsigned* b)
{
    asm volatile(
        "mma.sync.aligned.m16n8k16.row.col.f32.bf16.bf16.f32 "
        "{%0,%1,%2,%3}, {%4,%5,%6,%7}, {%8,%9}, {%0,%1,%2,%3};\n"
        : "+f"(c[0]), "+f"(c[1]), "+f"(c[2]), "+f"(c[3])
        : "r"(a[0]), "r"(a[1]), "r"(a[2]), "r"(a[3]), "r"(b[0]), "r"(b[1]));
}
__device__ __forceinline__ void stcs4(uint4* p, uint4 v) {
    asm volatile("st.global.cs.v4.u32 [%0], {%1,%2,%3,%4};"
                 :: "l"(p), "r"(v.x), "r"(v.y), "r"(v.z), "r"(v.w) : "memory");
}
__device__ __forceinline__ void stcs4f(float4* p, float4 v) {
    asm volatile("st.global.cs.v4.f32 [%0], {%1,%2,%3,%4};"
                 :: "l"(p), "f"(v.x), "f"(v.y), "f"(v.z), "f"(v.w) : "memory");
}

// ---------------------------------------------------------------------------
// Kernel 0: convert x (fp32) -> bf16 scratch
// ---------------------------------------------------------------------------
__global__ __launch_bounds__(256) void convert_bf16_kernel(const float* __restrict__ x)
{
    int i4 = blockIdx.x * 256 + threadIdx.x;
    float4 v = ((const float4*)x)[i4];
    __nv_bfloat162 lo = __floats2bfloat162_rn(v.x, v.y);
    __nv_bfloat162 hi = __floats2bfloat162_rn(v.z, v.w);
    uint2 packed;
    packed.x = *(unsigned*)&lo;
    packed.y = *(unsigned*)&hi;
    ((uint2*)g_xb)[i4] = packed;
}

// ---------------------------------------------------------------------------
// Kernel 1: sim = Xb * Xb^T, symmetric (bx >= by), ldmatrix + BK=64.
// 3-stage cp.async pipeline, commit every iteration (tail-safe).
// ---------------------------------------------------------------------------
#define BMg 128
#define BNg 128
#define BKg 64
#define BKP 72                          // 144 B rows: 9 x 16B, conflict-free LDSM
#define STAGES 3
#define A_UNITS (BMg * BKP)             // 9216 bf16
#define B_UNITS (BNg * BKP)
#define STAGE_UNITS (A_UNITS + B_UNITS) // 18432 bf16 = 36864 B
#define PIPE_BYTES (STAGES * STAGE_UNITS * 2)   // 110592
#define TILE_LD 136
#define EPI_BYTES (BMg * TILE_LD * 2)   // 34816
#define SMEM_GEMM PIPE_BYTES

__device__ __forceinline__ void issue_stage(uint32_t sA, uint32_t sB,
                                            int mbase, int nbase, int k0, int tid)
{
    // A and B: 128 rows x 8 x 16B chunks each -> 1024 ops per matrix, 4/thread
#pragma unroll
    for (int i = 0; i < 4; i++) {
        int id  = tid + i * 256;         // 0..1023
        int row = id >> 3;               // 0..127
        int c   = id & 7;                // 16B chunk within 128B row
        CP_ASYNC16(sA + row * 144 + c * 16,
                   g_xb + (size_t)(mbase + row) * D + k0 + c * 8);
        CP_ASYNC16(sB + row * 144 + c * 16,
                   g_xb + (size_t)(nbase + row) * D + k0 + c * 8);
    }
    CP_ASYNC_COMMIT();
}

__global__ __launch_bounds__(256) void gemm_sym_kernel()
{
    const int bx = blockIdx.x;
    const int by = blockIdx.y;
    if (by > bx) return;

    extern __shared__ __align__(16) char smem_raw[];
    __nv_bfloat16* smem = (__nv_bfloat16*)smem_raw;
    const uint32_t sb = smem_u32(smem);

    const int tid  = threadIdx.x;
    const int lane = tid & 31;
    const int wid  = tid >> 5;
    const int wm   = wid >> 2;
    const int wn   = wid & 3;
    const int g    = lane >> 2;
    const int t    = lane & 3;

    const int mbase = by * BMg;
    const int nbase = bx * BNg;

    // per-lane ldmatrix address offsets (bytes)
    const uint32_t aLaneOff = ((lane & 15) * BKP + (lane >> 4) * 8) * 2 +
                              (wm * 64) * BKP * 2;
    const uint32_t bLaneOff = ((lane & 7) * BKP + ((lane >> 3) & 1) * 8) * 2 +
                              (wn * 32) * BKP * 2;

    float acc[4][4][4];
#pragma unroll
    for (int i = 0; i < 4; i++)
#pragma unroll
        for (int j = 0; j < 4; j++)
#pragma unroll
            for (int q = 0; q < 4; q++) acc[i][j][q] = 0.0f;

#pragma unroll
    for (int s = 0; s < STAGES - 1; s++) {
        uint32_t base = sb + s * STAGE_UNITS * 2;
        issue_stage(base, base + A_UNITS * 2, mbase, nbase, s * BKg, tid);
    }

    const int NT = D / BKg;   // 8
    for (int kt = 0; kt < NT; kt++) {
        CP_ASYNC_WAIT1();
        __syncthreads();

        const int nk = kt + STAGES - 1;
        if (nk < NT) {
            uint32_t base = sb + (nk % STAGES) * STAGE_UNITS * 2;
            issue_stage(base, base + A_UNITS * 2, mbase, nbase, nk * BKg, tid);
        } else {
            CP_ASYNC_COMMIT();   // keep wait_group semantics in the tail
        }

        const uint32_t sA = sb + (kt % STAGES) * STAGE_UNITS * 2;
        const uint32_t sB = sA + A_UNITS * 2;
        const uint32_t aBase = sA + aLaneOff;
        const uint32_t bBase = sB + bLaneOff;

#pragma unroll
        for (int s = 0; s < 4; s++) {
            const uint32_t kOff = s * 32;   // 16 bf16 = 32 B per sub-step
            unsigned af[4][4], bfr[4][2];
#pragma unroll
            for (int i = 0; i < 4; i++)
                LDSM_X4(af[i][0], af[i][1], af[i][2], af[i][3],
                        aBase + i * (16 * BKP * 2) + kOff);
#pragma unroll
            for (int j = 0; j < 4; j++)
                LDSM_X2(bfr[j][0], bfr[j][1],
                        bBase + j * (8 * BKP * 2) + kOff);
#pragma unroll
            for (int i = 0; i < 4; i++)
#pragma unroll
                for (int j = 0; j < 4; j++)
                    mma_bf16(acc[i][j], af[i], bfr[j]);
        }
    }
    CP_ASYNC_WAIT0();
    __syncthreads();

    // stage bf16 tile in smem (reuse pipeline smem)
    __nv_bfloat16* tile = smem;
#pragma unroll
    for (int i = 0; i < 4; i++) {
#pragma unroll
        for (int j = 0; j < 4; j++) {
            const int r0 = wm * 64 + i * 16 + g;
            const int c  = wn * 32 + j * 8 + t * 2;
            __nv_bfloat162 v01 = __floats2bfloat162_rn(acc[i][j][0], acc[i][j][1]);
            __nv_bfloat162 v23 = __floats2bfloat162_rn(acc[i][j][2], acc[i][j][3]);
            *(__nv_bfloat162*)&tile[r0 * TILE_LD + c]       = v01;
            *(__nv_bfloat162*)&tile[(r0 + 8) * TILE_LD + c] = v23;
        }
    }
    __syncthreads();

    // direct write (streaming: sim has no L2 reuse at this scale)
#pragma unroll
    for (int kk = 0; kk < 8; kk++) {
        int u   = tid + kk * 256;
        int row = u >> 4;
        int seg = u & 15;
        stcs4((uint4*)(g_sim + (size_t)(mbase + row) * N + nbase + seg * 8),
              *(const uint4*)&tile[row * TILE_LD + seg * 8]);
    }

    // mirror write
    if (bx != by) {
        const int c = tid & 127;
        const int h = tid >> 7;
        __nv_bfloat16* dst = g_sim + (size_t)(nbase + c) * N + mbase + h * 64;
#pragma unroll
        for (int qq = 0; qq < 8; qq++) {
            uint32_t w[4];
#pragma unroll
            for (int p = 0; p < 2; p++) {
                int r = h * 64 + qq * 8 + p * 4;
                __nv_bfloat162 a, b;
                a.x = tile[(r + 0) * TILE_LD + c];
                a.y = tile[(r + 1) * TILE_LD + c];
                b.x = tile[(r + 2) * TILE_LD + c];
                b.y = tile[(r + 3) * TILE_LD + c];
                w[2 * p]     = *(uint32_t*)&a;
                w[2 * p + 1] = *(uint32_t*)&b;
            }
            stcs4((uint4*)(dst + qq * 8), make_uint4(w[0], w[1], w[2], w[3]));
        }
    }
}

// ---------------------------------------------------------------------------
// Kernel 2: histogram-threshold candidate selection (parallel suffix scan).
// ---------------------------------------------------------------------------
__global__ __launch_bounds__(256) void select_hist_kernel()
{
    __shared__ uint32_t rowbuf[N / 2];      // 16 KB
    __shared__ uint32_t hist[8192];         // 32 KB
    __shared__ int wsum[8];
    __shared__ int wexcl[8];
    __shared__ int sB, sCnt, sIdx;

    const int row  = blockIdx.x;
    const int tid  = threadIdx.x;
    const int lane = tid & 31;
    const int wid  = tid >> 5;

    // zero histogram
#pragma unroll
    for (int i = 0; i < 32; i++) hist[tid + i * 256] = 0;

    // load row (coalesced uint4, streaming)
    const uint4* src = (const uint4*)(g_sim + (size_t)row * N);
#pragma unroll
    for (int i = 0; i < 4; i++)
        ((uint4*)rowbuf)[tid + i * 256] = __ldcs(&src[tid + i * 256]);
    __syncthreads();

    // pass 1: histogram of 13-bit keys
#pragma unroll
    for (int i = 0; i < 16; i++) {
        uint32_t w = rowbuf[tid + i * 256];
        uint32_t lo = w & 0xFFFFu, hi = w >> 16;
        uint32_t klo = lo ^ ((lo & 0x8000u) ? 0xFFFFu : 0x8000u);
        uint32_t khi = hi ^ ((hi & 0x8000u) ? 0xFFFFu : 0x8000u);
        atomicAdd(&hist[klo >> 3], 1u);
        atomicAdd(&hist[khi >> 3], 1u);
    }
    if (tid == 0) sIdx = 0;
    __syncthreads();

    // chunk sum: thread t owns bins [t*32, t*32+32)
    int csum = 0;
    {
        const int b0 = tid * 32;
#pragma unroll
        for (int b = 0; b < 32; b++) csum += (int)hist[b0 + b];
    }

    // parallel suffix scan over 256 chunks (sum over chunks >= tid)
    int v = csum;
#pragma unroll
    for (int off = 1; off < 32; off <<= 1) {
        int n = __shfl_down_sync(0xffffffff, v, off);
        if (lane + off < 32) v += n;
    }
    if (lane == 0) wsum[wid] = v;     // warp-total
    __syncthreads();
    if (wid == 0 && lane < 8) {
        int wv = wsum[lane];
#pragma unroll
        for (int off = 1; off < 8; off <<= 1) {
            int n = __shfl_down_sync(0x000000ff, wv, off);
            if (lane + off < 8) wv += n;
        }
        wexcl[lane] = wv - wsum[lane];   // sum of warps strictly after
    }
    __syncthreads();

    const int S     = v + wexcl[wid];    // suffix incl own chunk
    const int Snext = S - csum;          // suffix excl own chunk

    // exactly one thread holds the boundary chunk
    if (S >= 32 && Snext < 32) {
        int cum = Snext;
        int b   = tid * 32 + 31;
        for (; b >= tid * 32; b--) {
            cum += (int)hist[b];
            if (cum >= 32) break;
        }
        sB = b;
        sCnt = cum;
    }
    __syncthreads();
    const uint32_t B = (uint32_t)sB;

    // pass 2: collect all with bin >= B
#pragma unroll
    for (int i = 0; i < 16; i++) {
        const int u = tid + i * 256;
        uint32_t w = rowbuf[u];
        uint32_t lo = w & 0xFFFFu, hi = w >> 16;
        uint32_t klo = lo ^ ((lo & 0x8000u) ? 0xFFFFu : 0x8000u);
        uint32_t khi = hi ^ ((hi & 0x8000u) ? 0xFFFFu : 0x8000u);
        if ((klo >> 3) >= B) {
            int slot = atomicAdd(&sIdx, 1);
            if (slot < CCAP) g_cand[row * CCAP + slot] = 2 * u;
        }
        if ((khi >> 3) >= B) {
            int slot = atomicAdd(&sIdx, 1);
            if (slot < CCAP) g_cand[row * CCAP + slot] = 2 * u + 1;
        }
    }
    __syncthreads();
    if (tid == 0) g_cnt[row] = (sCnt < CCAP) ? sCnt : CCAP;
}

// ---------------------------------------------------------------------------
// Kernel 3: exact fp32 rescore, top-16, streaming zero, scatter.
// ---------------------------------------------------------------------------
__global__ __launch_bounds__(256) void rescore_kernel(const float* __restrict__ x,
                                                      float* __restrict__ adj)
{
    __shared__ float xr[D];
    __shared__ float cv[CCAP];
    __shared__ int   ci[CCAP];

    const int row  = blockIdx.x;
    const int tid  = threadIdx.x;
    const int lane = tid & 31;
    const int wid  = tid >> 5;

    const int cnt = g_cnt[row];

    if (tid < CCAP) { cv[tid] = -INFINITY; ci[tid] = -1; }
    for (int k = tid; k < D; k += 256) xr[k] = x[(size_t)row * D + k];
    __syncthreads();

#pragma unroll
    for (int j = 0; j < CCAP / 8; j++) {
        const int c = wid + j * 8;
        if (c < cnt) {
            const int col = g_cand[row * CCAP + c];
            const float* xc = x + (size_t)col * D;
            float sum = 0.0f;
#pragma unroll
            for (int k = lane; k < D; k += 32) sum = fmaf(xr[k], xc[k], sum);
#pragma unroll
            for (int off = 16; off > 0; off >>= 1)
                sum += __shfl_down_sync(0xffffffff, sum, off);
            if (lane == 0) { cv[c] = sum; ci[c] = col; }
        }
    }
    __syncthreads();

    // zero the whole row with streaming stores (no L2 write-allocate churn)
    float4* rp = (float4*)(adj + (size_t)row * N);
    const float4 z = make_float4(0.f, 0.f, 0.f, 0.f);
    for (int u = tid; u < N / 4; u += 256) stcs4f(&rp[u], z);
    __syncthreads();

    // rank (value desc, col asc on tie) and scatter top-16
    if (tid < cnt) {
        const float v   = cv[tid];
        const int   col = ci[tid];
        int rank = 0;
#pragma unroll
        for (int j2 = 0; j2 < CCAP; j2++) {
            float vj = cv[j2];
            int   cj = ci[j2];
            rank += (vj > v) || (vj == v && cj < col);
        }
        if (rank < KSEL) adj[(size_t)row * N + col] = v;
    }
}

// ---------------------------------------------------------------------------
// Launch
// ---------------------------------------------------------------------------
extern "C" void kernel_launch(void* const* d_in, const int* in_sizes, int n_in,
                              void* d_out, int out_size)
{
    const float* x = (const float*)d_in[0];
    float* out = (float*)d_out;

    float* out_x   = out;
    float* out_adj = out + (size_t)N * D;

    cudaMemcpyAsync(out_x, x, (size_t)N * D * sizeof(float),
                    cudaMemcpyDeviceToDevice, 0);

    convert_bf16_kernel<<<(N * D) / 1024, 256>>>(x);

    cudaFuncSetAttribute(gemm_sym_kernel,
                         cudaFuncAttributeMaxDynamicSharedMemorySize, SMEM_GEMM);
    dim3 grid(N / BNg, N / BMg);
    gemm_sym_kernel<<<grid, 256, SMEM_GEMM>>>();

    select_hist_kernel<<<N, 256>>>();

    rescore_kernel<<<N, 256>>>(x, out_adj);
}

// round 10
// speedup vs baseline: 13.5193x; 2.0631x over previous
#include <cuda_runtime.h>
#include <cuda_bf16.h>
#include <math.h>
#include <stdint.h>

#define N 8192
#define D 512
#define KSEL 16
#define CCAP 64            // candidate capacity per row
#define FLOORC 64          // histogram floor code (sim >= 32.0)

// ---------------- static device scratch (no runtime allocation) -----------
__device__ __align__(16) __nv_bfloat16 g_xb[(size_t)N * D];        // 8 MB
__device__ __align__(16) uint8_t g_code[(size_t)N * N];            // 64 MB
__device__ int g_cand[N * CCAP];                                   // 2 MB
__device__ int g_cnt[N];

// ======================= helpers ==========================================
__device__ __forceinline__ uint32_t smem_u32(const void* p) {
    uint32_t a;
    asm("{ .reg .u64 t; cvta.to.shared.u64 t, %1; cvt.u32.u64 %0, t; }"
        : "=r"(a) : "l"(p));
    return a;
}
#define CP_ASYNC16(dst, src) \
    asm volatile("cp.async.cg.shared.global [%0], [%1], 16;" :: "r"(dst), "l"(src))
#define CP_ASYNC_COMMIT() asm volatile("cp.async.commit_group;" ::: "memory")
#define CP_ASYNC_WAIT1()  asm volatile("cp.async.wait_group 1;" ::: "memory")
#define CP_ASYNC_WAIT0()  asm volatile("cp.async.wait_group 0;" ::: "memory")

#define LDSM_X4(r0, r1, r2, r3, addr)                                        \
    asm volatile("ldmatrix.sync.aligned.m8n8.x4.shared.b16 {%0,%1,%2,%3}, [%4];" \
                 : "=r"(r0), "=r"(r1), "=r"(r2), "=r"(r3) : "r"(addr))
#define LDSM_X2(r0, r1, addr)                                                \
    asm volatile("ldmatrix.sync.aligned.m8n8.x2.shared.b16 {%0,%1}, [%2];"   \
                 : "=r"(r0), "=r"(r1) : "r"(addr))

__device__ __forceinline__ void mma_bf16(float* c, const unsigned* a, const unsigned* b)
{
    asm volatile(
        "mma.sync.aligned.m16n8k16.row.col.f32.bf16.bf16.f32 "
        "{%0,%1,%2,%3}, {%4,%5,%6,%7}, {%8,%9}, {%0,%1,%2,%3};\n"
        : "+f"(c[0]), "+f"(c[1]), "+f"(c[2]), "+f"(c[3])
        : "r"(a[0]), "r"(a[1]), "r"(a[2]), "r"(a[3]), "r"(b[0]), "r"(b[1]));
}
__device__ __forceinline__ void stcs4(uint4* p, uint4 v) {
    asm volatile("st.global.cs.v4.u32 [%0], {%1,%2,%3,%4};"
                 :: "l"(p), "r"(v.x), "r"(v.y), "r"(v.z), "r"(v.w) : "memory");
}
__device__ __forceinline__ void stcs4f(float4* p, float4 v) {
    asm volatile("st.global.cs.v4.f32 [%0], {%1,%2,%3,%4};"
                 :: "l"(p), "f"(v.x), "f"(v.y), "f"(v.z), "f"(v.w) : "memory");
}
// monotone fp32 -> uint8 code (0.5 resolution over [0, 127.5])
__device__ __forceinline__ uint32_t code_u8(float a) {
    int v = __float2int_rn(a * 2.0f);
    v = v < 0 ? 0 : (v > 255 ? 255 : v);
    return (uint32_t)v;
}

// ---------------------------------------------------------------------------
// Kernel 0: convert x (fp32) -> bf16 scratch
// ---------------------------------------------------------------------------
__global__ __launch_bounds__(256) void convert_bf16_kernel(const float* __restrict__ x)
{
    int i4 = blockIdx.x * 256 + threadIdx.x;
    float4 v = ((const float4*)x)[i4];
    __nv_bfloat162 lo = __floats2bfloat162_rn(v.x, v.y);
    __nv_bfloat162 hi = __floats2bfloat162_rn(v.z, v.w);
    uint2 packed;
    packed.x = *(unsigned*)&lo;
    packed.y = *(unsigned*)&hi;
    ((uint2*)g_xb)[i4] = packed;
}

// ---------------------------------------------------------------------------
// Kernel 1: codes = quantize(Xb * Xb^T), symmetric (bx >= by).
// ldmatrix + BK=64, 3-stage cp.async pipeline (commit every iteration).
// Epilogue emits uint8 codes; mirror tile written transposed.
// ---------------------------------------------------------------------------
#define BMg 128
#define BNg 128
#define BKg 64
#define BKP 72                          // 144 B rows: conflict-free LDSM
#define STAGES 3
#define A_UNITS (BMg * BKP)
#define B_UNITS (BNg * BKP)
#define STAGE_UNITS (A_UNITS + B_UNITS)
#define PIPE_BYTES (STAGES * STAGE_UNITS * 2)   // 110592
#define TLD 144                         // code-tile row stride (16B multiple)
#define SMEM_GEMM PIPE_BYTES

__device__ __forceinline__ void issue_stage(uint32_t sA, uint32_t sB,
                                            int mbase, int nbase, int k0, int tid)
{
#pragma unroll
    for (int i = 0; i < 4; i++) {
        int id  = tid + i * 256;
        int row = id >> 3;
        int c   = id & 7;
        CP_ASYNC16(sA + row * 144 + c * 16,
                   g_xb + (size_t)(mbase + row) * D + k0 + c * 8);
        CP_ASYNC16(sB + row * 144 + c * 16,
                   g_xb + (size_t)(nbase + row) * D + k0 + c * 8);
    }
    CP_ASYNC_COMMIT();
}

__global__ __launch_bounds__(256) void gemm_sym_kernel()
{
    const int bx = blockIdx.x;
    const int by = blockIdx.y;
    if (by > bx) return;

    extern __shared__ __align__(16) char smem_raw[];
    __nv_bfloat16* smem = (__nv_bfloat16*)smem_raw;
    const uint32_t sb = smem_u32(smem);

    const int tid  = threadIdx.x;
    const int lane = tid & 31;
    const int wid  = tid >> 5;
    const int wm   = wid >> 2;
    const int wn   = wid & 3;
    const int g    = lane >> 2;
    const int t    = lane & 3;

    const int mbase = by * BMg;
    const int nbase = bx * BNg;

    const uint32_t aLaneOff = ((lane & 15) * BKP + (lane >> 4) * 8) * 2 +
                              (wm * 64) * BKP * 2;
    const uint32_t bLaneOff = ((lane & 7) * BKP + ((lane >> 3) & 1) * 8) * 2 +
                              (wn * 32) * BKP * 2;

    float acc[4][4][4];
#pragma unroll
    for (int i = 0; i < 4; i++)
#pragma unroll
        for (int j = 0; j < 4; j++)
#pragma unroll
            for (int q = 0; q < 4; q++) acc[i][j][q] = 0.0f;

#pragma unroll
    for (int s = 0; s < STAGES - 1; s++) {
        uint32_t base = sb + s * STAGE_UNITS * 2;
        issue_stage(base, base + A_UNITS * 2, mbase, nbase, s * BKg, tid);
    }

    const int NT = D / BKg;   // 8
    for (int kt = 0; kt < NT; kt++) {
        CP_ASYNC_WAIT1();
        __syncthreads();

        const int nk = kt + STAGES - 1;
        if (nk < NT) {
            uint32_t base = sb + (nk % STAGES) * STAGE_UNITS * 2;
            issue_stage(base, base + A_UNITS * 2, mbase, nbase, nk * BKg, tid);
        } else {
            CP_ASYNC_COMMIT();   // tail-safe wait_group semantics
        }

        const uint32_t sA = sb + (kt % STAGES) * STAGE_UNITS * 2;
        const uint32_t sB = sA + A_UNITS * 2;
        const uint32_t aBase = sA + aLaneOff;
        const uint32_t bBase = sB + bLaneOff;

#pragma unroll
        for (int s = 0; s < 4; s++) {
            const uint32_t kOff = s * 32;
            unsigned af[4][4], bfr[4][2];
#pragma unroll
            for (int i = 0; i < 4; i++)
                LDSM_X4(af[i][0], af[i][1], af[i][2], af[i][3],
                        aBase + i * (16 * BKP * 2) + kOff);
#pragma unroll
            for (int j = 0; j < 4; j++)
                LDSM_X2(bfr[j][0], bfr[j][1],
                        bBase + j * (8 * BKP * 2) + kOff);
#pragma unroll
            for (int i = 0; i < 4; i++)
#pragma unroll
                for (int j = 0; j < 4; j++)
                    mma_bf16(acc[i][j], af[i], bfr[j]);
        }
    }
    CP_ASYNC_WAIT0();
    __syncthreads();

    // ---- stage uint8 code tile in smem (reuse pipeline smem) ----
    uint8_t* tile = (uint8_t*)smem;
#pragma unroll
    for (int i = 0; i < 4; i++) {
#pragma unroll
        for (int j = 0; j < 4; j++) {
            const int r0 = wm * 64 + i * 16 + g;
            const int c  = wn * 32 + j * 8 + t * 2;
            uint32_t p01 = code_u8(acc[i][j][0]) | (code_u8(acc[i][j][1]) << 8);
            uint32_t p23 = code_u8(acc[i][j][2]) | (code_u8(acc[i][j][3]) << 8);
            *(uint16_t*)&tile[r0 * TLD + c]       = (uint16_t)p01;
            *(uint16_t*)&tile[(r0 + 8) * TLD + c] = (uint16_t)p23;
        }
    }
    __syncthreads();

    // ---- direct write: 128 rows x 128 bytes (streaming) ----
#pragma unroll
    for (int kk = 0; kk < 4; kk++) {
        int u   = tid + kk * 256;       // 0..1023
        int row = u >> 3;
        int seg = u & 7;
        stcs4((uint4*)(g_code + (size_t)(mbase + row) * N + nbase + seg * 16),
              *(const uint4*)&tile[row * TLD + seg * 16]);
    }

    // ---- mirror write: transpose bytes ----
    if (bx != by) {
        const int c = tid & 127;
        const int h = tid >> 7;
        uint8_t* dst = g_code + (size_t)(nbase + c) * N + mbase + h * 64;
#pragma unroll
        for (int q = 0; q < 4; q++) {
            uint32_t w[4];
#pragma unroll
            for (int p = 0; p < 4; p++) {
                int rb = h * 64 + q * 16 + p * 4;
                uint32_t b0 = tile[(rb + 0) * TLD + c];
                uint32_t b1 = tile[(rb + 1) * TLD + c];
                uint32_t b2 = tile[(rb + 2) * TLD + c];
                uint32_t b3 = tile[(rb + 3) * TLD + c];
                w[p] = b0 | (b1 << 8) | (b2 << 16) | (b3 << 24);
            }
            stcs4((uint4*)(dst + q * 16), make_uint4(w[0], w[1], w[2], w[3]));
        }
    }
}

// ---------------------------------------------------------------------------
// Kernel 2: candidate selection on uint8 codes. 256-bin histogram with a
// floor predicate (code >= FLOORC); suffix scan in one warp; collect >= B.
// Fallback to full histogram if fewer than 32 entries above the floor
// (never taken for this data; kept for correctness).
// ---------------------------------------------------------------------------
__global__ __launch_bounds__(256) void select_code_kernel()
{
    __shared__ uint32_t rowbuf[2048];   // 8 KB: row of 8192 codes
    __shared__ int hist[256];
    __shared__ int totalHi, sB, sCnt, sIdx;

    const int row  = blockIdx.x;
    const int tid  = threadIdx.x;
    const int lane = tid & 31;
    const int wid  = tid >> 5;

    hist[tid] = 0;
    if (tid == 0) { sIdx = 0; totalHi = 0; }

    const uint4* src = (const uint4*)(g_code + (size_t)row * N);
    ((uint4*)rowbuf)[tid]       = __ldcs(&src[tid]);
    ((uint4*)rowbuf)[tid + 256] = __ldcs(&src[tid + 256]);
    __syncthreads();

    // pass 1: floored histogram
    int myc = 0;
#pragma unroll
    for (int i = 0; i < 8; i++) {
        uint32_t w = rowbuf[tid + i * 256];
#pragma unroll
        for (int b = 0; b < 4; b++) {
            uint32_t v = (w >> (8 * b)) & 255u;
            if (v >= FLOORC) { atomicAdd(&hist[v], 1); myc++; }
        }
    }
#pragma unroll
    for (int off = 16; off > 0; off >>= 1)
        myc += __shfl_down_sync(0xffffffff, myc, off);
    if (lane == 0) atomicAdd(&totalHi, myc);
    __syncthreads();

    // fallback: full histogram (correctness guard; not taken for this data)
    if (totalHi < 32) {
        hist[tid] = 0;
        __syncthreads();
#pragma unroll
        for (int i = 0; i < 8; i++) {
            uint32_t w = rowbuf[tid + i * 256];
#pragma unroll
            for (int b = 0; b < 4; b++)
                atomicAdd(&hist[(w >> (8 * b)) & 255u], 1);
        }
        __syncthreads();
    }

    // boundary scan: warp 0, lane l owns bins [8l, 8l+8)
    if (wid == 0) {
        const int b0 = lane * 8;
        int csum = 0;
#pragma unroll
        for (int k = 0; k < 8; k++) csum += hist[b0 + k];
        int v = csum;   // suffix sum over lanes >= lane
#pragma unroll
        for (int off = 1; off < 32; off <<= 1) {
            int n = __shfl_down_sync(0xffffffff, v, off);
            if (lane + off < 32) v += n;
        }
        int Snext = v - csum;
        if (v >= 32 && Snext < 32) {
            int cum = Snext;
            int b = b0 + 7;
            for (; b >= b0; b--) {
                cum += hist[b];
                if (cum >= 32) break;
            }
            sB = b;
            sCnt = cum;
        }
    }
    __syncthreads();
    const uint32_t B = (uint32_t)sB;

    // pass 2: collect all codes >= B
#pragma unroll
    for (int i = 0; i < 8; i++) {
        const int u = tid + i * 256;
        uint32_t w = rowbuf[u];
#pragma unroll
        for (int b = 0; b < 4; b++) {
            uint32_t v = (w >> (8 * b)) & 255u;
            if (v >= B) {
                int slot = atomicAdd(&sIdx, 1);
                if (slot < CCAP) g_cand[row * CCAP + slot] = 4 * u + b;
            }
        }
    }
    __syncthreads();
    if (tid == 0) g_cnt[row] = (sCnt < CCAP) ? sCnt : CCAP;
}

// ---------------------------------------------------------------------------
// Kernel 3: exact fp32 rescore, top-16, streaming zero, scatter.
// ---------------------------------------------------------------------------
__global__ __launch_bounds__(256) void rescore_kernel(const float* __restrict__ x,
                                                      float* __restrict__ adj)
{
    __shared__ float xr[D];
    __shared__ float cv[CCAP];
    __shared__ int   ci[CCAP];

    const int row  = blockIdx.x;
    const int tid  = threadIdx.x;
    const int lane = tid & 31;
    const int wid  = tid >> 5;

    const int cnt = g_cnt[row];

    if (tid < CCAP) { cv[tid] = -INFINITY; ci[tid] = -1; }
    for (int k = tid; k < D; k += 256) xr[k] = x[(size_t)row * D + k];
    __syncthreads();

#pragma unroll
    for (int j = 0; j < CCAP / 8; j++) {
        const int c = wid + j * 8;
        if (c < cnt) {
            const int col = g_cand[row * CCAP + c];
            const float* xc = x + (size_t)col * D;
            float sum = 0.0f;
#pragma unroll
            for (int k = lane; k < D; k += 32) sum = fmaf(xr[k], xc[k], sum);
#pragma unroll
            for (int off = 16; off > 0; off >>= 1)
                sum += __shfl_down_sync(0xffffffff, sum, off);
            if (lane == 0) { cv[c] = sum; ci[c] = col; }
        }
    }
    __syncthreads();

    // zero the whole row with streaming stores
    float4* rp = (float4*)(adj + (size_t)row * N);
    const float4 z = make_float4(0.f, 0.f, 0.f, 0.f);
    for (int u = tid; u < N / 4; u += 256) stcs4f(&rp[u], z);
    __syncthreads();

    // rank (value desc, col asc on tie) and scatter top-16
    if (tid < cnt) {
        const float v   = cv[tid];
        const int   col = ci[tid];
        int rank = 0;
#pragma unroll
        for (int j2 = 0; j2 < CCAP; j2++) {
            float vj = cv[j2];
            int   cj = ci[j2];
            rank += (vj > v) || (vj == v && cj < col);
        }
        if (rank < KSEL) adj[(size_t)row * N + col] = v;
    }
}

// ---------------------------------------------------------------------------
// Launch
// ---------------------------------------------------------------------------
extern "C" void kernel_launch(void* const* d_in, const int* in_sizes, int n_in,
                              void* d_out, int out_size)
{
    const float* x = (const float*)d_in[0];
    float* out = (float*)d_out;

    float* out_x   = out;
    float* out_adj = out + (size_t)N * D;

    cudaMemcpyAsync(out_x, x, (size_t)N * D * sizeof(float),
                    cudaMemcpyDeviceToDevice, 0);

    convert_bf16_kernel<<<(N * D) / 1024, 256>>>(x);

    cudaFuncSetAttribute(gemm_sym_kernel,
                         cudaFuncAttributeMaxDynamicSharedMemorySize, SMEM_GEMM);
    dim3 grid(N / BNg, N / BMg);
    gemm_sym_kernel<<<grid, 256, SMEM_GEMM>>>();

    select_code_kernel<<<N, 256>>>();

    rescore_kernel<<<N, 256>>>(x, out_adj);
}

// round 11
// speedup vs baseline: 13.5990x; 1.0059x over previous
#include <cuda_runtime.h>
#include <cuda_bf16.h>
#include <math.h>
#include <stdint.h>

#define N 8192
#define D 512
#define KSEL 16
#define CCAP 64            // candidate capacity per row
#define FLOORC 64          // histogram floor code (sim >= 32.0)

// ---------------- static device scratch (no runtime allocation) -----------
__device__ __align__(16) __nv_bfloat16 g_xb[(size_t)N * D];        // 8 MB
__device__ __align__(16) uint8_t g_code[(size_t)N * N];            // 64 MB
__device__ int g_cand[N * CCAP];                                   // 2 MB
__device__ int g_cnt[N];

// ======================= helpers ==========================================
__device__ __forceinline__ uint32_t smem_u32(const void* p) {
    uint32_t a;
    asm("{ .reg .u64 t; cvta.to.shared.u64 t, %1; cvt.u32.u64 %0, t; }"
        : "=r"(a) : "l"(p));
    return a;
}
#define CP_ASYNC16(dst, src) \
    asm volatile("cp.async.cg.shared.global [%0], [%1], 16;" :: "r"(dst), "l"(src))
#define CP_ASYNC_COMMIT() asm volatile("cp.async.commit_group;" ::: "memory")
#define CP_ASYNC_WAIT1()  asm volatile("cp.async.wait_group 1;" ::: "memory")
#define CP_ASYNC_WAIT0()  asm volatile("cp.async.wait_group 0;" ::: "memory")

#define LDSM_X4(r0, r1, r2, r3, addr)                                        \
    asm volatile("ldmatrix.sync.aligned.m8n8.x4.shared.b16 {%0,%1,%2,%3}, [%4];" \
                 : "=r"(r0), "=r"(r1), "=r"(r2), "=r"(r3) : "r"(addr))
#define LDSM_X2(r0, r1, addr)                                                \
    asm volatile("ldmatrix.sync.aligned.m8n8.x2.shared.b16 {%0,%1}, [%2];"   \
                 : "=r"(r0), "=r"(r1) : "r"(addr))

__device__ __forceinline__ void mma_bf16(float* c, const unsigned* a, const unsigned* b)
{
    asm volatile(
        "mma.sync.aligned.m16n8k16.row.col.f32.bf16.bf16.f32 "
        "{%0,%1,%2,%3}, {%4,%5,%6,%7}, {%8,%9}, {%0,%1,%2,%3};\n"
        : "+f"(c[0]), "+f"(c[1]), "+f"(c[2]), "+f"(c[3])
        : "r"(a[0]), "r"(a[1]), "r"(a[2]), "r"(a[3]), "r"(b[0]), "r"(b[1]));
}
__device__ __forceinline__ void stcs4(uint4* p, uint4 v) {
    asm volatile("st.global.cs.v4.u32 [%0], {%1,%2,%3,%4};"
                 :: "l"(p), "r"(v.x), "r"(v.y), "r"(v.z), "r"(v.w) : "memory");
}
__device__ __forceinline__ void stcs4f(float4* p, float4 v) {
    asm volatile("st.global.cs.v4.f32 [%0], {%1,%2,%3,%4};"
                 :: "l"(p), "f"(v.x), "f"(v.y), "f"(v.z), "f"(v.w) : "memory");
}
// monotone fp32 -> uint8 code (0.5 resolution over [0, 127.5])
__device__ __forceinline__ uint32_t code_u8(float a) {
    int v = __float2int_rn(a * 2.0f);
    v = v < 0 ? 0 : (v > 255 ? 255 : v);
    return (uint32_t)v;
}

// ---------------------------------------------------------------------------
// Kernel 0: convert x (fp32) -> bf16 scratch
// ---------------------------------------------------------------------------
__global__ __launch_bounds__(256) void convert_bf16_kernel(const float* __restrict__ x)
{
    int i4 = blockIdx.x * 256 + threadIdx.x;
    float4 v = ((const float4*)x)[i4];
    __nv_bfloat162 lo = __floats2bfloat162_rn(v.x, v.y);
    __nv_bfloat162 hi = __floats2bfloat162_rn(v.z, v.w);
    uint2 packed;
    packed.x = *(unsigned*)&lo;
    packed.y = *(unsigned*)&hi;
    ((uint2*)g_xb)[i4] = packed;
}

// ---------------------------------------------------------------------------
// Kernel 1: codes = quantize(Xb * Xb^T), symmetric (bx >= by).
// ldmatrix + BK=64, 3-stage cp.async pipeline (commit every iteration).
// 2 CTAs/SM for cross-CTA bubble filling.
// ---------------------------------------------------------------------------
#define BMg 128
#define BNg 128
#define BKg 64
#define BKP 72                          // 144 B rows: conflict-free LDSM
#define STAGES 3
#define A_UNITS (BMg * BKP)
#define B_UNITS (BNg * BKP)
#define STAGE_UNITS (A_UNITS + B_UNITS)
#define PIPE_BYTES (STAGES * STAGE_UNITS * 2)   // 110592
#define TLD 144                         // code-tile row stride
#define SMEM_GEMM PIPE_BYTES

__device__ __forceinline__ void issue_stage(uint32_t sA, uint32_t sB,
                                            int mbase, int nbase, int k0, int tid)
{
#pragma unroll
    for (int i = 0; i < 4; i++) {
        int id  = tid + i * 256;
        int row = id >> 3;
        int c   = id & 7;
        CP_ASYNC16(sA + row * 144 + c * 16,
                   g_xb + (size_t)(mbase + row) * D + k0 + c * 8);
        CP_ASYNC16(sB + row * 144 + c * 16,
                   g_xb + (size_t)(nbase + row) * D + k0 + c * 8);
    }
    CP_ASYNC_COMMIT();
}

__global__ __launch_bounds__(256, 2) void gemm_sym_kernel()
{
    const int bx = blockIdx.x;
    const int by = blockIdx.y;
    if (by > bx) return;

    extern __shared__ __align__(16) char smem_raw[];
    __nv_bfloat16* smem = (__nv_bfloat16*)smem_raw;
    const uint32_t sb = smem_u32(smem);

    const int tid  = threadIdx.x;
    const int lane = tid & 31;
    const int wid  = tid >> 5;
    const int wm   = wid >> 2;
    const int wn   = wid & 3;
    const int g    = lane >> 2;
    const int t    = lane & 3;

    const int mbase = by * BMg;
    const int nbase = bx * BNg;

    const uint32_t aLaneOff = ((lane & 15) * BKP + (lane >> 4) * 8) * 2 +
                              (wm * 64) * BKP * 2;
    const uint32_t bLaneOff = ((lane & 7) * BKP + ((lane >> 3) & 1) * 8) * 2 +
                              (wn * 32) * BKP * 2;

    float acc[4][4][4];
#pragma unroll
    for (int i = 0; i < 4; i++)
#pragma unroll
        for (int j = 0; j < 4; j++)
#pragma unroll
            for (int q = 0; q < 4; q++) acc[i][j][q] = 0.0f;

#pragma unroll
    for (int s = 0; s < STAGES - 1; s++) {
        uint32_t base = sb + s * STAGE_UNITS * 2;
        issue_stage(base, base + A_UNITS * 2, mbase, nbase, s * BKg, tid);
    }

    const int NT = D / BKg;   // 8
    for (int kt = 0; kt < NT; kt++) {
        CP_ASYNC_WAIT1();
        __syncthreads();

        const int nk = kt + STAGES - 1;
        if (nk < NT) {
            uint32_t base = sb + (nk % STAGES) * STAGE_UNITS * 2;
            issue_stage(base, base + A_UNITS * 2, mbase, nbase, nk * BKg, tid);
        } else {
            CP_ASYNC_COMMIT();   // tail-safe wait_group semantics
        }

        const uint32_t sA = sb + (kt % STAGES) * STAGE_UNITS * 2;
        const uint32_t sB = sA + A_UNITS * 2;
        const uint32_t aBase = sA + aLaneOff;
        const uint32_t bBase = sB + bLaneOff;

#pragma unroll
        for (int s = 0; s < 4; s++) {
            const uint32_t kOff = s * 32;
            unsigned af[4][4], bfr[4][2];
#pragma unroll
            for (int i = 0; i < 4; i++)
                LDSM_X4(af[i][0], af[i][1], af[i][2], af[i][3],
                        aBase + i * (16 * BKP * 2) + kOff);
#pragma unroll
            for (int j = 0; j < 4; j++)
                LDSM_X2(bfr[j][0], bfr[j][1],
                        bBase + j * (8 * BKP * 2) + kOff);
#pragma unroll
            for (int i = 0; i < 4; i++)
#pragma unroll
                for (int j = 0; j < 4; j++)
                    mma_bf16(acc[i][j], af[i], bfr[j]);
        }
    }
    CP_ASYNC_WAIT0();
    __syncthreads();

    // ---- stage uint8 code tile in smem (reuse pipeline smem) ----
    uint8_t* tile = (uint8_t*)smem;
#pragma unroll
    for (int i = 0; i < 4; i++) {
#pragma unroll
        for (int j = 0; j < 4; j++) {
            const int r0 = wm * 64 + i * 16 + g;
            const int c  = wn * 32 + j * 8 + t * 2;
            uint32_t p01 = code_u8(acc[i][j][0]) | (code_u8(acc[i][j][1]) << 8);
            uint32_t p23 = code_u8(acc[i][j][2]) | (code_u8(acc[i][j][3]) << 8);
            *(uint16_t*)&tile[r0 * TLD + c]       = (uint16_t)p01;
            *(uint16_t*)&tile[(r0 + 8) * TLD + c] = (uint16_t)p23;
        }
    }
    __syncthreads();

    // ---- direct write: 128 rows x 128 bytes (streaming) ----
#pragma unroll
    for (int kk = 0; kk < 4; kk++) {
        int u   = tid + kk * 256;
        int row = u >> 3;
        int seg = u & 7;
        stcs4((uint4*)(g_code + (size_t)(mbase + row) * N + nbase + seg * 16),
              *(const uint4*)&tile[row * TLD + seg * 16]);
    }

    // ---- mirror write: transpose bytes ----
    if (bx != by) {
        const int c = tid & 127;
        const int h = tid >> 7;
        uint8_t* dst = g_code + (size_t)(nbase + c) * N + mbase + h * 64;
#pragma unroll
        for (int q = 0; q < 4; q++) {
            uint32_t w[4];
#pragma unroll
            for (int p = 0; p < 4; p++) {
                int rb = h * 64 + q * 16 + p * 4;
                uint32_t b0 = tile[(rb + 0) * TLD + c];
                uint32_t b1 = tile[(rb + 1) * TLD + c];
                uint32_t b2 = tile[(rb + 2) * TLD + c];
                uint32_t b3 = tile[(rb + 3) * TLD + c];
                w[p] = b0 | (b1 << 8) | (b2 << 16) | (b3 << 24);
            }
            stcs4((uint4*)(dst + q * 16), make_uint4(w[0], w[1], w[2], w[3]));
        }
    }
}

// ---------------------------------------------------------------------------
// Kernel 2: candidate selection on uint8 codes (256-bin floored histogram).
// ---------------------------------------------------------------------------
__global__ __launch_bounds__(256) void select_code_kernel()
{
    __shared__ uint32_t rowbuf[2048];   // 8 KB
    __shared__ int hist[256];
    __shared__ int totalHi, sB, sCnt, sIdx;

    const int row  = blockIdx.x;
    const int tid  = threadIdx.x;
    const int lane = tid & 31;
    const int wid  = tid >> 5;

    hist[tid] = 0;
    if (tid == 0) { sIdx = 0; totalHi = 0; }

    const uint4* src = (const uint4*)(g_code + (size_t)row * N);
    ((uint4*)rowbuf)[tid]       = __ldcs(&src[tid]);
    ((uint4*)rowbuf)[tid + 256] = __ldcs(&src[tid + 256]);
    __syncthreads();

    // pass 1: floored histogram
    int myc = 0;
#pragma unroll
    for (int i = 0; i < 8; i++) {
        uint32_t w = rowbuf[tid + i * 256];
#pragma unroll
        for (int b = 0; b < 4; b++) {
            uint32_t v = (w >> (8 * b)) & 255u;
            if (v >= FLOORC) { atomicAdd(&hist[v], 1); myc++; }
        }
    }
#pragma unroll
    for (int off = 16; off > 0; off >>= 1)
        myc += __shfl_down_sync(0xffffffff, myc, off);
    if (lane == 0) atomicAdd(&totalHi, myc);
    __syncthreads();

    // fallback: full histogram (correctness guard)
    if (totalHi < 32) {
        hist[tid] = 0;
        __syncthreads();
#pragma unroll
        for (int i = 0; i < 8; i++) {
            uint32_t w = rowbuf[tid + i * 256];
#pragma unroll
            for (int b = 0; b < 4; b++)
                atomicAdd(&hist[(w >> (8 * b)) & 255u], 1);
        }
        __syncthreads();
    }

    // boundary scan in warp 0
    if (wid == 0) {
        const int b0 = lane * 8;
        int csum = 0;
#pragma unroll
        for (int k = 0; k < 8; k++) csum += hist[b0 + k];
        int v = csum;
#pragma unroll
        for (int off = 1; off < 32; off <<= 1) {
            int n = __shfl_down_sync(0xffffffff, v, off);
            if (lane + off < 32) v += n;
        }
        int Snext = v - csum;
        if (v >= 32 && Snext < 32) {
            int cum = Snext;
            int b = b0 + 7;
            for (; b >= b0; b--) {
                cum += hist[b];
                if (cum >= 32) break;
            }
            sB = b;
            sCnt = cum;
        }
    }
    __syncthreads();
    const uint32_t B = (uint32_t)sB;

    // pass 2: collect all codes >= B
#pragma unroll
    for (int i = 0; i < 8; i++) {
        const int u = tid + i * 256;
        uint32_t w = rowbuf[u];
#pragma unroll
        for (int b = 0; b < 4; b++) {
            uint32_t v = (w >> (8 * b)) & 255u;
            if (v >= B) {
                int slot = atomicAdd(&sIdx, 1);
                if (slot < CCAP) g_cand[row * CCAP + slot] = 4 * u + b;
            }
        }
    }
    __syncthreads();
    if (tid == 0) g_cnt[row] = (sCnt < CCAP) ? sCnt : CCAP;
}

// ---------------------------------------------------------------------------
// Kernel 3: exact fp32 rescore (float4 gathers), top-16, streaming zero.
// ---------------------------------------------------------------------------
__global__ __launch_bounds__(256) void rescore_kernel(const float* __restrict__ x,
                                                      float* __restrict__ adj)
{
    __shared__ __align__(16) float xr[D];
    __shared__ float cv[CCAP];
    __shared__ int   ci[CCAP];

    const int row  = blockIdx.x;
    const int tid  = threadIdx.x;
    const int lane = tid & 31;
    const int wid  = tid >> 5;

    const int cnt = g_cnt[row];

    if (tid < CCAP) { cv[tid] = -INFINITY; ci[tid] = -1; }
    // load x[row] (float4)
    {
        const float4* xs = (const float4*)(x + (size_t)row * D);
        if (tid < D / 4) ((float4*)xr)[tid] = xs[tid];
    }
    __syncthreads();

    const float4* xr4 = (const float4*)xr;
#pragma unroll
    for (int j = 0; j < CCAP / 8; j++) {
        const int c = wid + j * 8;
        if (c < cnt) {
            const int col = g_cand[row * CCAP + c];
            const float4* xc = (const float4*)(x + (size_t)col * D);
            float sum = 0.0f;
#pragma unroll
            for (int k = 0; k < D / 128; k++) {          // 4 iters
                float4 a = xr4[lane + k * 32];
                float4 b = xc[lane + k * 32];
                sum = fmaf(a.x, b.x, sum);
                sum = fmaf(a.y, b.y, sum);
                sum = fmaf(a.z, b.z, sum);
                sum = fmaf(a.w, b.w, sum);
            }
#pragma unroll
            for (int off = 16; off > 0; off >>= 1)
                sum += __shfl_down_sync(0xffffffff, sum, off);
            if (lane == 0) { cv[c] = sum; ci[c] = col; }
        }
    }
    __syncthreads();

    // zero the whole row with streaming stores
    float4* rp = (float4*)(adj + (size_t)row * N);
    const float4 z = make_float4(0.f, 0.f, 0.f, 0.f);
    for (int u = tid; u < N / 4; u += 256) stcs4f(&rp[u], z);
    __syncthreads();

    // rank (value desc, col asc on tie) and scatter top-16
    if (tid < cnt) {
        const float v   = cv[tid];
        const int   col = ci[tid];
        int rank = 0;
#pragma unroll
        for (int j2 = 0; j2 < CCAP; j2++) {
            float vj = cv[j2];
            int   cj = ci[j2];
            rank += (vj > v) || (vj == v && cj < col);
        }
        if (rank < KSEL) adj[(size_t)row * N + col] = v;
    }
}

// ---------------------------------------------------------------------------
// Launch
// ---------------------------------------------------------------------------
extern "C" void kernel_launch(void* const* d_in, const int* in_sizes, int n_in,
                              void* d_out, int out_size)
{
    const float* x = (const float*)d_in[0];
    float* out = (float*)d_out;

    float* out_x   = out;
    float* out_adj = out + (size_t)N * D;

    cudaMemcpyAsync(out_x, x, (size_t)N * D * sizeof(float),
                    cudaMemcpyDeviceToDevice, 0);

    convert_bf16_kernel<<<(N * D) / 1024, 256>>>(x);

    cudaFuncSetAttribute(gemm_sym_kernel,
                         cudaFuncAttributeMaxDynamicSharedMemorySize, SMEM_GEMM);
    dim3 grid(N / BNg, N / BMg);
    gemm_sym_kernel<<<grid, 256, SMEM_GEMM>>>();

    select_code_kernel<<<N, 256>>>();

    rescore_kernel<<<N, 256>>>(x, out_adj);
}